// round 7
// baseline (speedup 1.0000x reference)
#include <cuda_runtime.h>
#include <cstdint>
#include <cstddef>

#define N_NODES 100000
#define N_EDGES 1600000
#define F_IN    64
#define HIDDEN  128
#define N_GRAPHS 1024
#define EPS 1e-5f

#define SCAN_BLK 256
#define N_SCAN_BLOCKS ((N_NODES + SCAN_BLK - 1) / SCAN_BLK)   // 391
#define N_TILES ((N_NODES + 127) / 128)                        // 782

// ---------------- static scratch (no allocation allowed) ----------------
__device__ float g_hr[(size_t)N_NODES * HIDDEN];
__device__ float g_ho[(size_t)N_NODES * HIDDEN];
__device__ float g_ha[(size_t)N_NODES * HIDDEN];
__device__ float g_hb[(size_t)N_NODES * HIDDEN];

__device__ float g_scale[3][HIDDEN];
__device__ float g_shift[3][HIDDEN];

// tf32-split B fragments in mma.sync fragment order:
// [hilo][ks][ng][lane][16]  (16 = nt(8) x b(2))
// layer0 (K=64): 32768 floats, layer1/2 (K=128): 65536 floats each
__device__ __align__(16) float g_Bf[32768 + 65536 + 65536];

__device__ int   g_deg[N_NODES];
__device__ int   g_incl[N_SCAN_BLOCKS * SCAN_BLK];
__device__ int   g_bsum[N_SCAN_BLOCKS];
__device__ int   g_boff[N_SCAN_BLOCKS];
__device__ int   g_rowptr[N_NODES + 1];
__device__ int   g_cursor[N_NODES];
__device__ int   g_csr_src[N_EDGES];
__device__ float g_csr_ew[N_EDGES];

__device__ __forceinline__ uint32_t tf32_rn(float f) {
    uint32_t r;
    asm("cvt.rna.tf32.f32 %0, %1;" : "=r"(r) : "f"(f));
    return r;
}

// m16n8k8 tf32 MMA, f32 accumulate (sm_80+ baseline PTX -> HMMA on sm_103)
__device__ __forceinline__ void mma8(float* c, uint4 a, uint32_t b0, uint32_t b1) {
    asm volatile(
        "mma.sync.aligned.m16n8k8.row.col.f32.tf32.tf32.f32 "
        "{%0,%1,%2,%3}, {%4,%5,%6,%7}, {%8,%9}, {%0,%1,%2,%3};"
        : "+f"(c[0]), "+f"(c[1]), "+f"(c[2]), "+f"(c[3])
        : "r"(a.x), "r"(a.y), "r"(a.z), "r"(a.w), "r"(b0), "r"(b1));
}

// ======================= CSR build (by dst) ==============================
__global__ void hist_kernel(const int* __restrict__ dst, int* __restrict__ deg)
{
    int e = blockIdx.x * blockDim.x + threadIdx.x;
    if (e < N_EDGES) atomicAdd(deg + __ldg(dst + e), 1);
}

__global__ void scan1_kernel(const int* __restrict__ deg,
                             int* __restrict__ incl, int* __restrict__ bsum)
{
    __shared__ int s[SCAN_BLK];
    int gid = blockIdx.x * SCAN_BLK + threadIdx.x;
    int v = (gid < N_NODES) ? deg[gid] : 0;
    s[threadIdx.x] = v;
    __syncthreads();
    #pragma unroll
    for (int off = 1; off < SCAN_BLK; off <<= 1) {
        int t = (threadIdx.x >= off) ? s[threadIdx.x - off] : 0;
        __syncthreads();
        s[threadIdx.x] += t;
        __syncthreads();
    }
    incl[gid] = s[threadIdx.x];
    if (threadIdx.x == SCAN_BLK - 1) bsum[blockIdx.x] = s[threadIdx.x];
}

__global__ void scan2_kernel(const int* __restrict__ bsum, int* __restrict__ boff)
{
    __shared__ int s[512];
    int t = threadIdx.x;
    s[t] = (t < N_SCAN_BLOCKS) ? bsum[t] : 0;
    __syncthreads();
    #pragma unroll
    for (int off = 1; off < 512; off <<= 1) {
        int v = (t >= off) ? s[t - off] : 0;
        __syncthreads();
        s[t] += v;
        __syncthreads();
    }
    if (t < N_SCAN_BLOCKS) boff[t] = s[t] - bsum[t];
}

__global__ void scan3_kernel(const int* __restrict__ deg,
                             const int* __restrict__ incl,
                             const int* __restrict__ boff,
                             int* __restrict__ rowptr)
{
    int i = blockIdx.x * blockDim.x + threadIdx.x;
    if (i < N_NODES)
        rowptr[i] = incl[i] - deg[i] + boff[i / SCAN_BLK];
    if (i == 0) rowptr[N_NODES] = N_EDGES;
}

__global__ void fill_kernel(const int* __restrict__ src,
                            const int* __restrict__ dst,
                            const float* __restrict__ ew,
                            const int* __restrict__ rowptr,
                            int* __restrict__ cursor,
                            int* __restrict__ csr_src,
                            float* __restrict__ csr_ew)
{
    int e = blockIdx.x * blockDim.x + threadIdx.x;
    if (e >= N_EDGES) return;
    int d = __ldg(dst + e);
    int pos = atomicAdd(cursor + d, 1);
    int idx = __ldg(rowptr + d) + pos;
    csr_src[idx] = __ldg(src + e);
    csr_ew[idx]  = __ldg(ew + e);
}

// ---------------- fold BN params (+rel bias) into scale/shift -------------
__global__ void bn_fold_kernel(const float* __restrict__ br0, const float* __restrict__ g0,
                               const float* __restrict__ b0,  const float* __restrict__ m0,
                               const float* __restrict__ v0,
                               const float* __restrict__ br1, const float* __restrict__ g1,
                               const float* __restrict__ b1,  const float* __restrict__ m1,
                               const float* __restrict__ v1,
                               const float* __restrict__ br2, const float* __restrict__ g2,
                               const float* __restrict__ b2,  const float* __restrict__ m2,
                               const float* __restrict__ v2)
{
    int j = threadIdx.x;
    int l = blockIdx.x;
    const float* br = (l == 0) ? br0 : (l == 1) ? br1 : br2;
    const float* g  = (l == 0) ? g0  : (l == 1) ? g1  : g2;
    const float* b  = (l == 0) ? b0  : (l == 1) ? b1  : b2;
    const float* m  = (l == 0) ? m0  : (l == 1) ? m1  : m2;
    const float* v  = (l == 0) ? v0  : (l == 1) ? v1  : v2;
    float s = g[j] * rsqrtf(v[j] + EPS);
    g_scale[l][j] = s;
    g_shift[l][j] = (br[j] - m[j]) * s + b[j];
}

// -------- prep: tf32-split weights into mma fragment order ---------------
// element (hilo, ks, ng, lane, idx): nt=idx>>1, b=idx&1
//   k = ks*8 + (lane&3) + b*4 ; n = ng*64 + nt*8 + (lane>>2)
__global__ void prep_weights_kernel(const float* __restrict__ Wr0, const float* __restrict__ Wo0,
                                    const float* __restrict__ Wr1, const float* __restrict__ Wo1,
                                    const float* __restrict__ Wr2, const float* __restrict__ Wo2)
{
    int id = blockIdx.x * blockDim.x + threadIdx.x;
    int total = 32768 + 65536 + 65536;
    if (id >= total) return;
    int K, base, rem;
    const float *Wr, *Wo;
    if (id < 32768)          { K = 64;  base = 0;     rem = id;          Wr = Wr0; Wo = Wo0; }
    else if (id < 98304)     { K = 128; base = 32768; rem = id - 32768;  Wr = Wr1; Wo = Wo1; }
    else                     { K = 128; base = 98304; rem = id - 98304;  Wr = Wr2; Wo = Wo2; }
    int KS = K / 8;
    int idx  = rem & 15;
    int lane = (rem >> 4) & 31;
    int ng   = (rem >> 9) & 3;
    int t    = rem >> 11;
    int ks   = t % KS;
    int hilo = t / KS;
    int nt = idx >> 1, b = idx & 1;
    int k = ks * 8 + (lane & 3) + b * 4;
    int n = ng * 64 + nt * 8 + (lane >> 2);
    float wv = (n < 128) ? __ldg(Wr + k * 128 + n) : __ldg(Wo + k * 128 + (n - 128));
    uint32_t hi = tf32_rn(wv);
    uint32_t out = hilo ? tf32_rn(wv - __uint_as_float(hi)) : hi;
    g_Bf[base + rem] = __uint_as_float(out);
}

// ====== tensor-core dual GEMM via mma.sync tf32 (3-term split) ===========
// CTA: 128-node tile x 256 cols, 16 warps; warp (mg=w>>2, ng=w&3) does
// rows [mg*32, +32), cols [ng*64, +64). K = KS*8.
// smem: raw tile 128 x (K+4) floats, then A-frag area K*256 floats laid as
// [mg][ks][chunk(4: mt*2+hilo)][lane][4] (LDS.128 conflict-free).
template <int KS>
__global__ void __launch_bounds__(512, 1)
gemm_mma_kernel(const float* __restrict__ h,
                const float* __restrict__ Bf,
                float* __restrict__ hr,
                float* __restrict__ ho)
{
    constexpr int K = KS * 8;
    extern __shared__ float smem[];
    float* sRaw  = smem;                      // 128*(K+4) floats
    float* sFrag = smem + 128 * (K + 4);      // K*256 floats

    const int tid  = threadIdx.x;
    const int w    = tid >> 5;
    const int lane = tid & 31;
    const int mg   = w >> 2;
    const int ng   = w & 3;
    const int n0   = blockIdx.x * 128;

    // ---- stage raw activation tile (coalesced uint4) ----
    for (int i = tid; i < 32 * K; i += 512) {       // 32*K uint4 = 128*K floats
        int row = i / (K / 4);
        int c   = i % (K / 4);
        uint4 v = make_uint4(0u, 0u, 0u, 0u);
        if (n0 + row < N_NODES)
            v = *reinterpret_cast<const uint4*>(h + (size_t)(n0 + row) * K + c * 4);
        *reinterpret_cast<uint4*>(&sRaw[row * (K + 4) + c * 4]) = v;
    }
    __syncthreads();

    // ---- convert to tf32 hi/lo A fragments (warp handles mg, ks = ng+4j) ----
    uint32_t* fragU = reinterpret_cast<uint32_t*>(sFrag);
    for (int j = 0; j < KS / 4; j++) {
        int ks = ng + 4 * j;
        #pragma unroll
        for (int mt = 0; mt < 2; mt++) {
            #pragma unroll
            for (int r = 0; r < 4; r++) {
                int row = mg * 32 + mt * 16 + (lane >> 2) + (r & 1) * 8;
                int k   = ks * 8 + (lane & 3) + ((r >> 1) & 1) * 4;
                float x = sRaw[row * (K + 4) + k];
                uint32_t hi = tf32_rn(x);
                uint32_t lo = tf32_rn(x - __uint_as_float(hi));
                int cbase = ((mg * KS + ks) * 4);
                fragU[((cbase + mt * 2 + 0) * 32 + lane) * 4 + r] = hi;
                fragU[((cbase + mt * 2 + 1) * 32 + lane) * 4 + r] = lo;
            }
        }
    }
    __syncthreads();

    // ---- MMA mainloop ----
    float acc[2][8][4];
    #pragma unroll
    for (int mt = 0; mt < 2; mt++)
        #pragma unroll
        for (int nt = 0; nt < 8; nt++)
            #pragma unroll
            for (int r = 0; r < 4; r++) acc[mt][nt][r] = 0.f;

    const uint4* fragQ = reinterpret_cast<const uint4*>(sFrag);
    const uint4* BfQ   = reinterpret_cast<const uint4*>(Bf);

    for (int ks = 0; ks < KS; ks++) {
        const uint4* aB = fragQ + ((mg * KS + ks) * 4) * 32 + lane;
        uint4 a0h = aB[0 * 32];
        uint4 a0l = aB[1 * 32];
        uint4 a1h = aB[2 * 32];
        uint4 a1l = aB[3 * 32];

        // B hi fragments: [hilo=0][ks][ng][lane][16] -> 4 x uint4
        const uint4* bHiB = BfQ + (((0 * KS + ks) * 4 + ng) * 32 + lane) * 4;
        uint4 bh0 = __ldg(bHiB + 0);
        uint4 bh1 = __ldg(bHiB + 1);
        uint4 bh2 = __ldg(bHiB + 2);
        uint4 bh3 = __ldg(bHiB + 3);

        // pass hh + lh (share Bhi)
        mma8(acc[0][0], a0h, bh0.x, bh0.y);  mma8(acc[0][1], a0h, bh0.z, bh0.w);
        mma8(acc[0][2], a0h, bh1.x, bh1.y);  mma8(acc[0][3], a0h, bh1.z, bh1.w);
        mma8(acc[0][4], a0h, bh2.x, bh2.y);  mma8(acc[0][5], a0h, bh2.z, bh2.w);
        mma8(acc[0][6], a0h, bh3.x, bh3.y);  mma8(acc[0][7], a0h, bh3.z, bh3.w);
        mma8(acc[1][0], a1h, bh0.x, bh0.y);  mma8(acc[1][1], a1h, bh0.z, bh0.w);
        mma8(acc[1][2], a1h, bh1.x, bh1.y);  mma8(acc[1][3], a1h, bh1.z, bh1.w);
        mma8(acc[1][4], a1h, bh2.x, bh2.y);  mma8(acc[1][5], a1h, bh2.z, bh2.w);
        mma8(acc[1][6], a1h, bh3.x, bh3.y);  mma8(acc[1][7], a1h, bh3.z, bh3.w);

        mma8(acc[0][0], a0l, bh0.x, bh0.y);  mma8(acc[0][1], a0l, bh0.z, bh0.w);
        mma8(acc[0][2], a0l, bh1.x, bh1.y);  mma8(acc[0][3], a0l, bh1.z, bh1.w);
        mma8(acc[0][4], a0l, bh2.x, bh2.y);  mma8(acc[0][5], a0l, bh2.z, bh2.w);
        mma8(acc[0][6], a0l, bh3.x, bh3.y);  mma8(acc[0][7], a0l, bh3.z, bh3.w);
        mma8(acc[1][0], a1l, bh0.x, bh0.y);  mma8(acc[1][1], a1l, bh0.z, bh0.w);
        mma8(acc[1][2], a1l, bh1.x, bh1.y);  mma8(acc[1][3], a1l, bh1.z, bh1.w);
        mma8(acc[1][4], a1l, bh2.x, bh2.y);  mma8(acc[1][5], a1l, bh2.z, bh2.w);
        mma8(acc[1][6], a1l, bh3.x, bh3.y);  mma8(acc[1][7], a1l, bh3.z, bh3.w);

        // B lo fragments
        const uint4* bLoB = BfQ + (((1 * KS + ks) * 4 + ng) * 32 + lane) * 4;
        uint4 bl0 = __ldg(bLoB + 0);
        uint4 bl1 = __ldg(bLoB + 1);
        uint4 bl2 = __ldg(bLoB + 2);
        uint4 bl3 = __ldg(bLoB + 3);

        // pass hl
        mma8(acc[0][0], a0h, bl0.x, bl0.y);  mma8(acc[0][1], a0h, bl0.z, bl0.w);
        mma8(acc[0][2], a0h, bl1.x, bl1.y);  mma8(acc[0][3], a0h, bl1.z, bl1.w);
        mma8(acc[0][4], a0h, bl2.x, bl2.y);  mma8(acc[0][5], a0h, bl2.z, bl2.w);
        mma8(acc[0][6], a0h, bl3.x, bl3.y);  mma8(acc[0][7], a0h, bl3.z, bl3.w);
        mma8(acc[1][0], a1h, bl0.x, bl0.y);  mma8(acc[1][1], a1h, bl0.z, bl0.w);
        mma8(acc[1][2], a1h, bl1.x, bl1.y);  mma8(acc[1][3], a1h, bl1.z, bl1.w);
        mma8(acc[1][4], a1h, bl2.x, bl2.y);  mma8(acc[1][5], a1h, bl2.z, bl2.w);
        mma8(acc[1][6], a1h, bl3.x, bl3.y);  mma8(acc[1][7], a1h, bl3.z, bl3.w);
    }

    // ---- epilogue: acc -> hr / ho ----
    float* dst = (ng < 2) ? hr : ho;
    const int colbase = (ng & 1) * 64;
    #pragma unroll
    for (int mt = 0; mt < 2; mt++) {
        int row = n0 + mg * 32 + mt * 16 + (lane >> 2);
        #pragma unroll
        for (int nt = 0; nt < 8; nt++) {
            int col = colbase + nt * 8 + 2 * (lane & 3);
            if (row < N_NODES)
                *reinterpret_cast<float2*>(dst + (size_t)row * 128 + col) =
                    make_float2(acc[mt][nt][0], acc[mt][nt][1]);
            if (row + 8 < N_NODES)
                *reinterpret_cast<float2*>(dst + (size_t)(row + 8) * 128 + col) =
                    make_float2(acc[mt][nt][2], acc[mt][nt][3]);
        }
    }
}

#define GEMM_SMEM(K) ((128 * ((K) + 4) + (K) * 256) * 4)

// === fused gather + root + BN + ReLU:  out = relu((Σ ew*hr[src] + ho)*s + t)
__global__ void gather_fused_kernel(const float* __restrict__ hr,
                                    const float* __restrict__ ho,
                                    const int* __restrict__ rowptr,
                                    const int* __restrict__ csr_src,
                                    const float* __restrict__ csr_ew,
                                    const float* __restrict__ scale,
                                    const float* __restrict__ shift,
                                    float* __restrict__ out)
{
    int node = (blockIdx.x * blockDim.x + threadIdx.x) >> 5;
    if (node >= N_NODES) return;
    int lane = threadIdx.x & 31;
    int beg = __ldg(rowptr + node);
    int end = __ldg(rowptr + node + 1);

    const float4* hr4 = reinterpret_cast<const float4*>(hr);
    float4 acc = *(reinterpret_cast<const float4*>(ho + (size_t)node * 128) + lane);

    int i = beg;
    for (; i + 3 < end; i += 4) {
        int   s0 = __ldg(csr_src + i);
        int   s1 = __ldg(csr_src + i + 1);
        int   s2 = __ldg(csr_src + i + 2);
        int   s3 = __ldg(csr_src + i + 3);
        float e0 = __ldg(csr_ew + i);
        float e1 = __ldg(csr_ew + i + 1);
        float e2 = __ldg(csr_ew + i + 2);
        float e3 = __ldg(csr_ew + i + 3);
        float4 v0 = hr4[(size_t)s0 * 32 + lane];
        float4 v1 = hr4[(size_t)s1 * 32 + lane];
        float4 v2 = hr4[(size_t)s2 * 32 + lane];
        float4 v3 = hr4[(size_t)s3 * 32 + lane];
        acc.x = fmaf(v0.x, e0, acc.x); acc.y = fmaf(v0.y, e0, acc.y);
        acc.z = fmaf(v0.z, e0, acc.z); acc.w = fmaf(v0.w, e0, acc.w);
        acc.x = fmaf(v1.x, e1, acc.x); acc.y = fmaf(v1.y, e1, acc.y);
        acc.z = fmaf(v1.z, e1, acc.z); acc.w = fmaf(v1.w, e1, acc.w);
        acc.x = fmaf(v2.x, e2, acc.x); acc.y = fmaf(v2.y, e2, acc.y);
        acc.z = fmaf(v2.z, e2, acc.z); acc.w = fmaf(v2.w, e2, acc.w);
        acc.x = fmaf(v3.x, e3, acc.x); acc.y = fmaf(v3.y, e3, acc.y);
        acc.z = fmaf(v3.z, e3, acc.z); acc.w = fmaf(v3.w, e3, acc.w);
    }
    for (; i < end; i++) {
        int   s0 = __ldg(csr_src + i);
        float e0 = __ldg(csr_ew + i);
        float4 v0 = hr4[(size_t)s0 * 32 + lane];
        acc.x = fmaf(v0.x, e0, acc.x); acc.y = fmaf(v0.y, e0, acc.y);
        acc.z = fmaf(v0.z, e0, acc.z); acc.w = fmaf(v0.w, e0, acc.w);
    }

    float4 sc = *(reinterpret_cast<const float4*>(scale) + lane);
    float4 sh = *(reinterpret_cast<const float4*>(shift) + lane);
    float4 res;
    res.x = fmaxf(fmaf(acc.x, sc.x, sh.x), 0.f);
    res.y = fmaxf(fmaf(acc.y, sc.y, sh.y), 0.f);
    res.z = fmaxf(fmaf(acc.z, sc.z, sh.z), 0.f);
    res.w = fmaxf(fmaf(acc.w, sc.w, sh.w), 0.f);
    *(reinterpret_cast<float4*>(out + (size_t)node * 128) + lane) = res;
}

// ------------- fused mean-pool + head (block per graph) ------------------
__global__ void pool_head_kernel(const float* __restrict__ h,
                                 const int* __restrict__ batch,
                                 const float* __restrict__ W1,
                                 const float* __restrict__ b1,
                                 const float* __restrict__ W2,
                                 const float* __restrict__ b2,
                                 float* __restrict__ out)
{
    __shared__ float sp[HIDDEN];
    __shared__ float sred[128];
    __shared__ int srange[2];
    const int g = blockIdx.x;
    const int t = threadIdx.x;

    if (t < 2) {
        int key = g + t;
        int lo = 0, hi = N_NODES;
        while (lo < hi) {
            int mid = (lo + hi) >> 1;
            if (__ldg(batch + mid) < key) lo = mid + 1; else hi = mid;
        }
        srange[t] = lo;
    }
    __syncthreads();
    const int start = srange[0];
    const int end   = srange[1];

    float sum = 0.f;
    for (int n = start; n < end; n++)
        sum += h[(size_t)n * HIDDEN + t];
    float inv = 1.0f / fmaxf((float)(end - start), 1.0f);
    sp[t] = sum * inv;
    __syncthreads();

    float val = 0.f;
    if (t < 64) {
        float acc = __ldg(b1 + t);
        #pragma unroll 8
        for (int k = 0; k < HIDDEN; k++)
            acc = fmaf(sp[k], __ldg(W1 + k * 64 + t), acc);
        val = fmaxf(acc, 0.f) * __ldg(W2 + t);
    }
    sred[t] = val;
    __syncthreads();
    for (int s = 64; s > 0; s >>= 1) {
        if (t < s) sred[t] += sred[t + s];
        __syncthreads();
    }
    if (t == 0) out[g] = sred[0] + __ldg(b2);
}

// -------------------------------------------------------------------------
extern "C" void kernel_launch(void* const* d_in, const int* in_sizes, int n_in,
                              void* d_out, int out_size)
{
    (void)in_sizes; (void)n_in; (void)out_size;
    const float* x     = (const float*)d_in[0];
    const int*   ei    = (const int*)  d_in[1];
    const float* ea    = (const float*)d_in[2];
    const int*   batch = (const int*)  d_in[3];
    const float* P[21];
    for (int i = 0; i < 21; i++) P[i] = (const float*)d_in[4 + i];
    const float* head_w1 = (const float*)d_in[25];
    const float* head_b1 = (const float*)d_in[26];
    const float* head_w2 = (const float*)d_in[27];
    const float* head_b2 = (const float*)d_in[28];
    float* out = (float*)d_out;

    float *hr, *ho, *ha, *hb, *scale, *shift, *Bf;
    int *deg, *incl, *bsum, *boff, *rowptr, *cursor, *csr_src;
    float *csr_ew;
    cudaGetSymbolAddress((void**)&hr,      g_hr);
    cudaGetSymbolAddress((void**)&ho,      g_ho);
    cudaGetSymbolAddress((void**)&ha,      g_ha);
    cudaGetSymbolAddress((void**)&hb,      g_hb);
    cudaGetSymbolAddress((void**)&scale,   g_scale);
    cudaGetSymbolAddress((void**)&shift,   g_shift);
    cudaGetSymbolAddress((void**)&Bf,      g_Bf);
    cudaGetSymbolAddress((void**)&deg,     g_deg);
    cudaGetSymbolAddress((void**)&incl,    g_incl);
    cudaGetSymbolAddress((void**)&bsum,    g_bsum);
    cudaGetSymbolAddress((void**)&boff,    g_boff);
    cudaGetSymbolAddress((void**)&rowptr,  g_rowptr);
    cudaGetSymbolAddress((void**)&cursor,  g_cursor);
    cudaGetSymbolAddress((void**)&csr_src, g_csr_src);
    cudaGetSymbolAddress((void**)&csr_ew,  g_csr_ew);

    cudaFuncSetAttribute(gemm_mma_kernel<8>,
                         cudaFuncAttributeMaxDynamicSharedMemorySize, GEMM_SMEM(64));
    cudaFuncSetAttribute(gemm_mma_kernel<16>,
                         cudaFuncAttributeMaxDynamicSharedMemorySize, GEMM_SMEM(128));

    const int* src = ei;
    const int* dst = ei + N_EDGES;

    const int gather_blocks = (N_NODES * 32 + 255) / 256;

    // Launch order chosen so the 6th launch (ncu -s 5 -c 1) is gemm layer 0.
    prep_weights_kernel<<<(32768 + 65536 + 65536 + 255) / 256, 256>>>(
        P[0], P[2], P[7], P[9], P[14], P[16]);                       // 1
    cudaMemsetAsync(deg,    0, N_NODES * sizeof(int), 0);            // 2
    cudaMemsetAsync(cursor, 0, N_NODES * sizeof(int), 0);            // 3
    hist_kernel<<<(N_EDGES + 255) / 256, 256>>>(dst, deg);           // 4
    scan1_kernel<<<N_SCAN_BLOCKS, SCAN_BLK>>>(deg, incl, bsum);      // 5
    gemm_mma_kernel<8><<<N_TILES, 512, GEMM_SMEM(64)>>>(x, Bf, hr, ho);   // 6 (profiled)
    scan2_kernel<<<1, 512>>>(bsum, boff);                            // 7
    scan3_kernel<<<(N_NODES + 255) / 256, 256>>>(deg, incl, boff, rowptr); // 8
    fill_kernel<<<(N_EDGES + 255) / 256, 256>>>(src, dst, ea, rowptr, cursor,
                                                csr_src, csr_ew);    // 9
    bn_fold_kernel<<<3, 128>>>(P[1], P[3], P[4], P[5], P[6],
                               P[8], P[10], P[11], P[12], P[13],
                               P[15], P[17], P[18], P[19], P[20]);   // 10

    // ---- Layer 0 gather ----
    gather_fused_kernel<<<gather_blocks, 256>>>(hr, ho, rowptr, csr_src, csr_ew,
                                                scale + 0 * HIDDEN, shift + 0 * HIDDEN, ha);

    // ---- Layer 1 ----
    gemm_mma_kernel<16><<<N_TILES, 512, GEMM_SMEM(128)>>>(ha, Bf + 32768, hr, ho);
    gather_fused_kernel<<<gather_blocks, 256>>>(hr, ho, rowptr, csr_src, csr_ew,
                                                scale + 1 * HIDDEN, shift + 1 * HIDDEN, hb);

    // ---- Layer 2 ----
    gemm_mma_kernel<16><<<N_TILES, 512, GEMM_SMEM(128)>>>(hb, Bf + 98304, hr, ho);
    gather_fused_kernel<<<gather_blocks, 256>>>(hr, ho, rowptr, csr_src, csr_ew,
                                                scale + 2 * HIDDEN, shift + 2 * HIDDEN, ha);

    // ---- Fused mean pool + head ----
    pool_head_kernel<<<N_GRAPHS, 128>>>(ha, batch, head_w1, head_b1,
                                        head_w2, head_b2, out);
}

// round 8
// speedup vs baseline: 1.1170x; 1.1170x over previous
#include <cuda_runtime.h>
#include <cstdint>
#include <cstddef>

#define N_NODES 100000
#define N_EDGES 1600000
#define F_IN    64
#define HIDDEN  128
#define N_GRAPHS 1024
#define EPS 1e-5f

#define SCAN_BLK 256
#define N_SCAN_BLOCKS ((N_NODES + SCAN_BLK - 1) / SCAN_BLK)   // 391
#define N_TILES64 ((N_NODES + 63) / 64)                        // 1563

// ---------------- static scratch (no allocation allowed) ----------------
__device__ float g_hr[(size_t)N_NODES * HIDDEN];
__device__ float g_ho[(size_t)N_NODES * HIDDEN];
__device__ float g_ha[(size_t)N_NODES * HIDDEN];
__device__ float g_hb[(size_t)N_NODES * HIDDEN];

__device__ float g_scale[3][HIDDEN];
__device__ float g_shift[3][HIDDEN];

// tf32-split B fragments in mma.sync fragment order:
// [hilo][ks][ng][lane][16]  (16 = nt(8) x b(2))
__device__ __align__(16) float g_Bf[32768 + 65536 + 65536];

__device__ int   g_deg[N_NODES];
__device__ int   g_incl[N_SCAN_BLOCKS * SCAN_BLK];
__device__ int   g_bsum[N_SCAN_BLOCKS];
__device__ int   g_boff[N_SCAN_BLOCKS];
__device__ int   g_rowptr[N_NODES + 1];
__device__ int   g_cursor[N_NODES];
__device__ int   g_csr_src[N_EDGES];
__device__ float g_csr_ew[N_EDGES];

__device__ __forceinline__ uint32_t tf32_rn(float f) {
    uint32_t r;
    asm("cvt.rna.tf32.f32 %0, %1;" : "=r"(r) : "f"(f));
    return r;
}

// m16n8k8 tf32 MMA, f32 accumulate (sm_80+ baseline PTX -> HMMA on sm_103)
__device__ __forceinline__ void mma8(float* c, uint4 a, uint32_t b0, uint32_t b1) {
    asm volatile(
        "mma.sync.aligned.m16n8k8.row.col.f32.tf32.tf32.f32 "
        "{%0,%1,%2,%3}, {%4,%5,%6,%7}, {%8,%9}, {%0,%1,%2,%3};"
        : "+f"(c[0]), "+f"(c[1]), "+f"(c[2]), "+f"(c[3])
        : "r"(a.x), "r"(a.y), "r"(a.z), "r"(a.w), "r"(b0), "r"(b1));
}

// ======================= CSR build (by dst) ==============================
__global__ void hist_kernel(const int* __restrict__ dst, int* __restrict__ deg)
{
    int e = blockIdx.x * blockDim.x + threadIdx.x;
    if (e < N_EDGES) atomicAdd(deg + __ldg(dst + e), 1);
}

__global__ void scan1_kernel(const int* __restrict__ deg,
                             int* __restrict__ incl, int* __restrict__ bsum)
{
    __shared__ int s[SCAN_BLK];
    int gid = blockIdx.x * SCAN_BLK + threadIdx.x;
    int v = (gid < N_NODES) ? deg[gid] : 0;
    s[threadIdx.x] = v;
    __syncthreads();
    #pragma unroll
    for (int off = 1; off < SCAN_BLK; off <<= 1) {
        int t = (threadIdx.x >= off) ? s[threadIdx.x - off] : 0;
        __syncthreads();
        s[threadIdx.x] += t;
        __syncthreads();
    }
    incl[gid] = s[threadIdx.x];
    if (threadIdx.x == SCAN_BLK - 1) bsum[blockIdx.x] = s[threadIdx.x];
}

__global__ void scan2_kernel(const int* __restrict__ bsum, int* __restrict__ boff)
{
    __shared__ int s[512];
    int t = threadIdx.x;
    s[t] = (t < N_SCAN_BLOCKS) ? bsum[t] : 0;
    __syncthreads();
    #pragma unroll
    for (int off = 1; off < 512; off <<= 1) {
        int v = (t >= off) ? s[t - off] : 0;
        __syncthreads();
        s[t] += v;
        __syncthreads();
    }
    if (t < N_SCAN_BLOCKS) boff[t] = s[t] - bsum[t];
}

__global__ void scan3_kernel(const int* __restrict__ deg,
                             const int* __restrict__ incl,
                             const int* __restrict__ boff,
                             int* __restrict__ rowptr)
{
    int i = blockIdx.x * blockDim.x + threadIdx.x;
    if (i < N_NODES)
        rowptr[i] = incl[i] - deg[i] + boff[i / SCAN_BLK];
    if (i == 0) rowptr[N_NODES] = N_EDGES;
}

__global__ void fill_kernel(const int* __restrict__ src,
                            const int* __restrict__ dst,
                            const float* __restrict__ ew,
                            const int* __restrict__ rowptr,
                            int* __restrict__ cursor,
                            int* __restrict__ csr_src,
                            float* __restrict__ csr_ew)
{
    int e = blockIdx.x * blockDim.x + threadIdx.x;
    if (e >= N_EDGES) return;
    int d = __ldg(dst + e);
    int pos = atomicAdd(cursor + d, 1);
    int idx = __ldg(rowptr + d) + pos;
    csr_src[idx] = __ldg(src + e);
    csr_ew[idx]  = __ldg(ew + e);
}

// ---------------- fold BN params (+rel bias) into scale/shift -------------
__global__ void bn_fold_kernel(const float* __restrict__ br0, const float* __restrict__ g0,
                               const float* __restrict__ b0,  const float* __restrict__ m0,
                               const float* __restrict__ v0,
                               const float* __restrict__ br1, const float* __restrict__ g1,
                               const float* __restrict__ b1,  const float* __restrict__ m1,
                               const float* __restrict__ v1,
                               const float* __restrict__ br2, const float* __restrict__ g2,
                               const float* __restrict__ b2,  const float* __restrict__ m2,
                               const float* __restrict__ v2)
{
    int j = threadIdx.x;
    int l = blockIdx.x;
    const float* br = (l == 0) ? br0 : (l == 1) ? br1 : br2;
    const float* g  = (l == 0) ? g0  : (l == 1) ? g1  : g2;
    const float* b  = (l == 0) ? b0  : (l == 1) ? b1  : b2;
    const float* m  = (l == 0) ? m0  : (l == 1) ? m1  : m2;
    const float* v  = (l == 0) ? v0  : (l == 1) ? v1  : v2;
    float s = g[j] * rsqrtf(v[j] + EPS);
    g_scale[l][j] = s;
    g_shift[l][j] = (br[j] - m[j]) * s + b[j];
}

// -------- prep: tf32-split weights into mma fragment order ---------------
__global__ void prep_weights_kernel(const float* __restrict__ Wr0, const float* __restrict__ Wo0,
                                    const float* __restrict__ Wr1, const float* __restrict__ Wo1,
                                    const float* __restrict__ Wr2, const float* __restrict__ Wo2)
{
    int id = blockIdx.x * blockDim.x + threadIdx.x;
    int total = 32768 + 65536 + 65536;
    if (id >= total) return;
    int K, base, rem;
    const float *Wr, *Wo;
    if (id < 32768)          { K = 64;  base = 0;     rem = id;          Wr = Wr0; Wo = Wo0; }
    else if (id < 98304)     { K = 128; base = 32768; rem = id - 32768;  Wr = Wr1; Wo = Wo1; }
    else                     { K = 128; base = 98304; rem = id - 98304;  Wr = Wr2; Wo = Wo2; }
    int KS = K / 8;
    int idx  = rem & 15;
    int lane = (rem >> 4) & 31;
    int ng   = (rem >> 9) & 3;
    int t    = rem >> 11;
    int ks   = t % KS;
    int hilo = t / KS;
    int nt = idx >> 1, b = idx & 1;
    int k = ks * 8 + (lane & 3) + b * 4;
    int n = ng * 64 + nt * 8 + (lane >> 2);
    float wv = (n < 128) ? __ldg(Wr + k * 128 + n) : __ldg(Wo + k * 128 + (n - 128));
    uint32_t hi = tf32_rn(wv);
    uint32_t out = hilo ? tf32_rn(wv - __uint_as_float(hi)) : hi;
    g_Bf[base + rem] = __uint_as_float(out);
}

// ====== tensor-core dual GEMM via mma.sync tf32 (3-term split) ===========
// CTA: 64-node tile x 256 cols, 8 warps (256 thr), 2 CTAs/SM co-resident.
// warp (mg=w>>2 in {0,1}, ng=w&3) does rows [mg*32,+32), cols [ng*64,+64).
// smem: raw 64x(K+4) floats, then A-frag K*128 floats as
// [mg][ks][chunk(4: mt*2+hilo)][lane][4] (LDS.128 conflict-free).
template <int KS>
__global__ void __launch_bounds__(256, 2)
gemm_mma_kernel(const float* __restrict__ h,
                const float* __restrict__ Bf,
                float* __restrict__ hr,
                float* __restrict__ ho)
{
    constexpr int K = KS * 8;
    extern __shared__ float smem[];
    float* sRaw  = smem;                      // 64*(K+4) floats
    float* sFrag = smem + 64 * (K + 4);       // K*128 floats

    const int tid  = threadIdx.x;
    const int w    = tid >> 5;
    const int lane = tid & 31;
    const int mg   = w >> 2;                  // 0..1
    const int ng   = w & 3;                   // 0..3
    const int n0   = blockIdx.x * 64;

    // ---- stage raw activation tile (coalesced uint4) ----
    for (int i = tid; i < 16 * K; i += 256) {       // 16*K uint4 = 64*K floats
        int row = i / (K / 4);
        int c   = i % (K / 4);
        uint4 v = make_uint4(0u, 0u, 0u, 0u);
        if (n0 + row < N_NODES)
            v = *reinterpret_cast<const uint4*>(h + (size_t)(n0 + row) * K + c * 4);
        *reinterpret_cast<uint4*>(&sRaw[row * (K + 4) + c * 4]) = v;
    }
    __syncthreads();

    // ---- convert to tf32 hi/lo A fragments (warp handles mg, ks = ng+4j) ----
    uint32_t* fragU = reinterpret_cast<uint32_t*>(sFrag);
    for (int j = 0; j < KS / 4; j++) {
        int ks = ng + 4 * j;
        #pragma unroll
        for (int mt = 0; mt < 2; mt++) {
            #pragma unroll
            for (int r = 0; r < 4; r++) {
                int row = mg * 32 + mt * 16 + (lane >> 2) + (r & 1) * 8;
                int k   = ks * 8 + (lane & 3) + ((r >> 1) & 1) * 4;
                float x = sRaw[row * (K + 4) + k];
                uint32_t hi = tf32_rn(x);
                uint32_t lo = tf32_rn(x - __uint_as_float(hi));
                int cbase = ((mg * KS + ks) * 4);
                fragU[((cbase + mt * 2 + 0) * 32 + lane) * 4 + r] = hi;
                fragU[((cbase + mt * 2 + 1) * 32 + lane) * 4 + r] = lo;
            }
        }
    }
    __syncthreads();

    // ---- MMA mainloop ----
    float acc[2][8][4];
    #pragma unroll
    for (int mt = 0; mt < 2; mt++)
        #pragma unroll
        for (int nt = 0; nt < 8; nt++)
            #pragma unroll
            for (int r = 0; r < 4; r++) acc[mt][nt][r] = 0.f;

    const uint4* fragQ = reinterpret_cast<const uint4*>(sFrag);
    const uint4* BfQ   = reinterpret_cast<const uint4*>(Bf);

    for (int ks = 0; ks < KS; ks++) {
        const uint4* aB = fragQ + ((mg * KS + ks) * 4) * 32 + lane;
        uint4 a0h = aB[0 * 32];
        uint4 a0l = aB[1 * 32];
        uint4 a1h = aB[2 * 32];
        uint4 a1l = aB[3 * 32];

        const uint4* bHiB = BfQ + (((0 * KS + ks) * 4 + ng) * 32 + lane) * 4;
        uint4 bh0 = __ldg(bHiB + 0);
        uint4 bh1 = __ldg(bHiB + 1);
        uint4 bh2 = __ldg(bHiB + 2);
        uint4 bh3 = __ldg(bHiB + 3);

        // pass hh + lh (share Bhi)
        mma8(acc[0][0], a0h, bh0.x, bh0.y);  mma8(acc[0][1], a0h, bh0.z, bh0.w);
        mma8(acc[0][2], a0h, bh1.x, bh1.y);  mma8(acc[0][3], a0h, bh1.z, bh1.w);
        mma8(acc[0][4], a0h, bh2.x, bh2.y);  mma8(acc[0][5], a0h, bh2.z, bh2.w);
        mma8(acc[0][6], a0h, bh3.x, bh3.y);  mma8(acc[0][7], a0h, bh3.z, bh3.w);
        mma8(acc[1][0], a1h, bh0.x, bh0.y);  mma8(acc[1][1], a1h, bh0.z, bh0.w);
        mma8(acc[1][2], a1h, bh1.x, bh1.y);  mma8(acc[1][3], a1h, bh1.z, bh1.w);
        mma8(acc[1][4], a1h, bh2.x, bh2.y);  mma8(acc[1][5], a1h, bh2.z, bh2.w);
        mma8(acc[1][6], a1h, bh3.x, bh3.y);  mma8(acc[1][7], a1h, bh3.z, bh3.w);

        mma8(acc[0][0], a0l, bh0.x, bh0.y);  mma8(acc[0][1], a0l, bh0.z, bh0.w);
        mma8(acc[0][2], a0l, bh1.x, bh1.y);  mma8(acc[0][3], a0l, bh1.z, bh1.w);
        mma8(acc[0][4], a0l, bh2.x, bh2.y);  mma8(acc[0][5], a0l, bh2.z, bh2.w);
        mma8(acc[0][6], a0l, bh3.x, bh3.y);  mma8(acc[0][7], a0l, bh3.z, bh3.w);
        mma8(acc[1][0], a1l, bh0.x, bh0.y);  mma8(acc[1][1], a1l, bh0.z, bh0.w);
        mma8(acc[1][2], a1l, bh1.x, bh1.y);  mma8(acc[1][3], a1l, bh1.z, bh1.w);
        mma8(acc[1][4], a1l, bh2.x, bh2.y);  mma8(acc[1][5], a1l, bh2.z, bh2.w);
        mma8(acc[1][6], a1l, bh3.x, bh3.y);  mma8(acc[1][7], a1l, bh3.z, bh3.w);

        const uint4* bLoB = BfQ + (((1 * KS + ks) * 4 + ng) * 32 + lane) * 4;
        uint4 bl0 = __ldg(bLoB + 0);
        uint4 bl1 = __ldg(bLoB + 1);
        uint4 bl2 = __ldg(bLoB + 2);
        uint4 bl3 = __ldg(bLoB + 3);

        // pass hl
        mma8(acc[0][0], a0h, bl0.x, bl0.y);  mma8(acc[0][1], a0h, bl0.z, bl0.w);
        mma8(acc[0][2], a0h, bl1.x, bl1.y);  mma8(acc[0][3], a0h, bl1.z, bl1.w);
        mma8(acc[0][4], a0h, bl2.x, bl2.y);  mma8(acc[0][5], a0h, bl2.z, bl2.w);
        mma8(acc[0][6], a0h, bl3.x, bl3.y);  mma8(acc[0][7], a0h, bl3.z, bl3.w);
        mma8(acc[1][0], a1h, bl0.x, bl0.y);  mma8(acc[1][1], a1h, bl0.z, bl0.w);
        mma8(acc[1][2], a1h, bl1.x, bl1.y);  mma8(acc[1][3], a1h, bl1.z, bl1.w);
        mma8(acc[1][4], a1h, bl2.x, bl2.y);  mma8(acc[1][5], a1h, bl2.z, bl2.w);
        mma8(acc[1][6], a1h, bl3.x, bl3.y);  mma8(acc[1][7], a1h, bl3.z, bl3.w);
    }

    // ---- epilogue: acc -> hr / ho ----
    float* dst = (ng < 2) ? hr : ho;
    const int colbase = (ng & 1) * 64;
    #pragma unroll
    for (int mt = 0; mt < 2; mt++) {
        int row = n0 + mg * 32 + mt * 16 + (lane >> 2);
        #pragma unroll
        for (int nt = 0; nt < 8; nt++) {
            int col = colbase + nt * 8 + 2 * (lane & 3);
            if (row < N_NODES)
                *reinterpret_cast<float2*>(dst + (size_t)row * 128 + col) =
                    make_float2(acc[mt][nt][0], acc[mt][nt][1]);
            if (row + 8 < N_NODES)
                *reinterpret_cast<float2*>(dst + (size_t)(row + 8) * 128 + col) =
                    make_float2(acc[mt][nt][2], acc[mt][nt][3]);
        }
    }
}

#define GEMM_SMEM(K) ((64 * ((K) + 4) + (K) * 128) * 4)

// === fused gather + root + BN + ReLU:  out = relu((Σ ew*hr[src] + ho)*s + t)
__global__ void gather_fused_kernel(const float* __restrict__ hr,
                                    const float* __restrict__ ho,
                                    const int* __restrict__ rowptr,
                                    const int* __restrict__ csr_src,
                                    const float* __restrict__ csr_ew,
                                    const float* __restrict__ scale,
                                    const float* __restrict__ shift,
                                    float* __restrict__ out)
{
    int node = (blockIdx.x * blockDim.x + threadIdx.x) >> 5;
    if (node >= N_NODES) return;
    int lane = threadIdx.x & 31;
    int beg = __ldg(rowptr + node);
    int end = __ldg(rowptr + node + 1);

    const float4* hr4 = reinterpret_cast<const float4*>(hr);
    float4 acc = *(reinterpret_cast<const float4*>(ho + (size_t)node * 128) + lane);

    int i = beg;
    for (; i + 3 < end; i += 4) {
        int   s0 = __ldg(csr_src + i);
        int   s1 = __ldg(csr_src + i + 1);
        int   s2 = __ldg(csr_src + i + 2);
        int   s3 = __ldg(csr_src + i + 3);
        float e0 = __ldg(csr_ew + i);
        float e1 = __ldg(csr_ew + i + 1);
        float e2 = __ldg(csr_ew + i + 2);
        float e3 = __ldg(csr_ew + i + 3);
        float4 v0 = hr4[(size_t)s0 * 32 + lane];
        float4 v1 = hr4[(size_t)s1 * 32 + lane];
        float4 v2 = hr4[(size_t)s2 * 32 + lane];
        float4 v3 = hr4[(size_t)s3 * 32 + lane];
        acc.x = fmaf(v0.x, e0, acc.x); acc.y = fmaf(v0.y, e0, acc.y);
        acc.z = fmaf(v0.z, e0, acc.z); acc.w = fmaf(v0.w, e0, acc.w);
        acc.x = fmaf(v1.x, e1, acc.x); acc.y = fmaf(v1.y, e1, acc.y);
        acc.z = fmaf(v1.z, e1, acc.z); acc.w = fmaf(v1.w, e1, acc.w);
        acc.x = fmaf(v2.x, e2, acc.x); acc.y = fmaf(v2.y, e2, acc.y);
        acc.z = fmaf(v2.z, e2, acc.z); acc.w = fmaf(v2.w, e2, acc.w);
        acc.x = fmaf(v3.x, e3, acc.x); acc.y = fmaf(v3.y, e3, acc.y);
        acc.z = fmaf(v3.z, e3, acc.z); acc.w = fmaf(v3.w, e3, acc.w);
    }
    for (; i < end; i++) {
        int   s0 = __ldg(csr_src + i);
        float e0 = __ldg(csr_ew + i);
        float4 v0 = hr4[(size_t)s0 * 32 + lane];
        acc.x = fmaf(v0.x, e0, acc.x); acc.y = fmaf(v0.y, e0, acc.y);
        acc.z = fmaf(v0.z, e0, acc.z); acc.w = fmaf(v0.w, e0, acc.w);
    }

    float4 sc = *(reinterpret_cast<const float4*>(scale) + lane);
    float4 sh = *(reinterpret_cast<const float4*>(shift) + lane);
    float4 res;
    res.x = fmaxf(fmaf(acc.x, sc.x, sh.x), 0.f);
    res.y = fmaxf(fmaf(acc.y, sc.y, sh.y), 0.f);
    res.z = fmaxf(fmaf(acc.z, sc.z, sh.z), 0.f);
    res.w = fmaxf(fmaf(acc.w, sc.w, sh.w), 0.f);
    *(reinterpret_cast<float4*>(out + (size_t)node * 128) + lane) = res;
}

// ------------- fused mean-pool + head (block per graph) ------------------
__global__ void pool_head_kernel(const float* __restrict__ h,
                                 const int* __restrict__ batch,
                                 const float* __restrict__ W1,
                                 const float* __restrict__ b1,
                                 const float* __restrict__ W2,
                                 const float* __restrict__ b2,
                                 float* __restrict__ out)
{
    __shared__ float sp[HIDDEN];
    __shared__ float sred[128];
    __shared__ int srange[2];
    const int g = blockIdx.x;
    const int t = threadIdx.x;

    if (t < 2) {
        int key = g + t;
        int lo = 0, hi = N_NODES;
        while (lo < hi) {
            int mid = (lo + hi) >> 1;
            if (__ldg(batch + mid) < key) lo = mid + 1; else hi = mid;
        }
        srange[t] = lo;
    }
    __syncthreads();
    const int start = srange[0];
    const int end   = srange[1];

    float sum = 0.f;
    for (int n = start; n < end; n++)
        sum += h[(size_t)n * HIDDEN + t];
    float inv = 1.0f / fmaxf((float)(end - start), 1.0f);
    sp[t] = sum * inv;
    __syncthreads();

    float val = 0.f;
    if (t < 64) {
        float acc = __ldg(b1 + t);
        #pragma unroll 8
        for (int k = 0; k < HIDDEN; k++)
            acc = fmaf(sp[k], __ldg(W1 + k * 64 + t), acc);
        val = fmaxf(acc, 0.f) * __ldg(W2 + t);
    }
    sred[t] = val;
    __syncthreads();
    for (int s = 64; s > 0; s >>= 1) {
        if (t < s) sred[t] += sred[t + s];
        __syncthreads();
    }
    if (t == 0) out[g] = sred[0] + __ldg(b2);
}

// -------------------------------------------------------------------------
extern "C" void kernel_launch(void* const* d_in, const int* in_sizes, int n_in,
                              void* d_out, int out_size)
{
    (void)in_sizes; (void)n_in; (void)out_size;
    const float* x     = (const float*)d_in[0];
    const int*   ei    = (const int*)  d_in[1];
    const float* ea    = (const float*)d_in[2];
    const int*   batch = (const int*)  d_in[3];
    const float* P[21];
    for (int i = 0; i < 21; i++) P[i] = (const float*)d_in[4 + i];
    const float* head_w1 = (const float*)d_in[25];
    const float* head_b1 = (const float*)d_in[26];
    const float* head_w2 = (const float*)d_in[27];
    const float* head_b2 = (const float*)d_in[28];
    float* out = (float*)d_out;

    float *hr, *ho, *ha, *hb, *scale, *shift, *Bf;
    int *deg, *incl, *bsum, *boff, *rowptr, *cursor, *csr_src;
    float *csr_ew;
    cudaGetSymbolAddress((void**)&hr,      g_hr);
    cudaGetSymbolAddress((void**)&ho,      g_ho);
    cudaGetSymbolAddress((void**)&ha,      g_ha);
    cudaGetSymbolAddress((void**)&hb,      g_hb);
    cudaGetSymbolAddress((void**)&scale,   g_scale);
    cudaGetSymbolAddress((void**)&shift,   g_shift);
    cudaGetSymbolAddress((void**)&Bf,      g_Bf);
    cudaGetSymbolAddress((void**)&deg,     g_deg);
    cudaGetSymbolAddress((void**)&incl,    g_incl);
    cudaGetSymbolAddress((void**)&bsum,    g_bsum);
    cudaGetSymbolAddress((void**)&boff,    g_boff);
    cudaGetSymbolAddress((void**)&rowptr,  g_rowptr);
    cudaGetSymbolAddress((void**)&cursor,  g_cursor);
    cudaGetSymbolAddress((void**)&csr_src, g_csr_src);
    cudaGetSymbolAddress((void**)&csr_ew,  g_csr_ew);

    cudaFuncSetAttribute(gemm_mma_kernel<8>,
                         cudaFuncAttributeMaxDynamicSharedMemorySize, GEMM_SMEM(64));
    cudaFuncSetAttribute(gemm_mma_kernel<16>,
                         cudaFuncAttributeMaxDynamicSharedMemorySize, GEMM_SMEM(128));

    const int* src = ei;
    const int* dst = ei + N_EDGES;

    const int gather_blocks = (N_NODES * 32 + 255) / 256;

    // Launch order: 6th launch (ncu -s 5 -c 1) is gemm layer 0.
    prep_weights_kernel<<<(32768 + 65536 + 65536 + 255) / 256, 256>>>(
        P[0], P[2], P[7], P[9], P[14], P[16]);                       // 1
    cudaMemsetAsync(deg,    0, N_NODES * sizeof(int), 0);            // 2
    cudaMemsetAsync(cursor, 0, N_NODES * sizeof(int), 0);            // 3
    hist_kernel<<<(N_EDGES + 255) / 256, 256>>>(dst, deg);           // 4
    scan1_kernel<<<N_SCAN_BLOCKS, SCAN_BLK>>>(deg, incl, bsum);      // 5
    gemm_mma_kernel<8><<<N_TILES64, 256, GEMM_SMEM(64)>>>(x, Bf, hr, ho); // 6 (profiled)
    scan2_kernel<<<1, 512>>>(bsum, boff);                            // 7
    scan3_kernel<<<(N_NODES + 255) / 256, 256>>>(deg, incl, boff, rowptr); // 8
    fill_kernel<<<(N_EDGES + 255) / 256, 256>>>(src, dst, ea, rowptr, cursor,
                                                csr_src, csr_ew);    // 9
    bn_fold_kernel<<<3, 128>>>(P[1], P[3], P[4], P[5], P[6],
                               P[8], P[10], P[11], P[12], P[13],
                               P[15], P[17], P[18], P[19], P[20]);   // 10

    // ---- Layer 0 gather ----
    gather_fused_kernel<<<gather_blocks, 256>>>(hr, ho, rowptr, csr_src, csr_ew,
                                                scale + 0 * HIDDEN, shift + 0 * HIDDEN, ha);

    // ---- Layer 1 ----
    gemm_mma_kernel<16><<<N_TILES64, 256, GEMM_SMEM(128)>>>(ha, Bf + 32768, hr, ho);
    gather_fused_kernel<<<gather_blocks, 256>>>(hr, ho, rowptr, csr_src, csr_ew,
                                                scale + 1 * HIDDEN, shift + 1 * HIDDEN, hb);

    // ---- Layer 2 ----
    gemm_mma_kernel<16><<<N_TILES64, 256, GEMM_SMEM(128)>>>(hb, Bf + 98304, hr, ho);
    gather_fused_kernel<<<gather_blocks, 256>>>(hr, ho, rowptr, csr_src, csr_ew,
                                                scale + 2 * HIDDEN, shift + 2 * HIDDEN, ha);

    // ---- Fused mean pool + head ----
    pool_head_kernel<<<N_GRAPHS, 128>>>(ha, batch, head_w1, head_b1,
                                        head_w2, head_b2, out);
}

// round 9
// speedup vs baseline: 1.4075x; 1.2601x over previous
#include <cuda_runtime.h>
#include <cstdint>
#include <cstddef>

#define N_NODES 100000
#define N_EDGES 1600000
#define F_IN    64
#define HIDDEN  128
#define N_GRAPHS 1024
#define EPS 1e-5f

#define SCAN_BLK 256
#define N_SCAN_BLOCKS ((N_NODES + SCAN_BLK - 1) / SCAN_BLK)   // 391
#define N_TILES64 ((N_NODES + 63) / 64)                        // 1563

// ---------------- static scratch (no allocation allowed) ----------------
__device__ float g_hr[(size_t)N_NODES * HIDDEN];
__device__ float g_ho[(size_t)N_NODES * HIDDEN];
__device__ float g_ha[(size_t)N_NODES * HIDDEN];
__device__ float g_hb[(size_t)N_NODES * HIDDEN];

__device__ float g_scale[3][HIDDEN];
__device__ float g_shift[3][HIDDEN];

// bf16-split B fragments in m16n8k16 fragment order (packed bf16x2 words):
// [hilo][ks16][ng][lane][16]  (16 = nt(8) x breg(2))
// layer0 (K=64): 16384 words, layer1/2 (K=128): 32768 words each
__device__ __align__(16) uint32_t g_Bf[16384 + 32768 + 32768];

__device__ int   g_deg[N_NODES];
__device__ int   g_incl[N_SCAN_BLOCKS * SCAN_BLK];
__device__ int   g_bsum[N_SCAN_BLOCKS];
__device__ int   g_boff[N_SCAN_BLOCKS];
__device__ int   g_rowptr[N_NODES + 1];
__device__ int   g_cursor[N_NODES];
__device__ int   g_csr_src[N_EDGES];
__device__ float g_csr_ew[N_EDGES];

// pack two floats to bf16x2 word: low half = x0, high half = x1
__device__ __forceinline__ uint32_t bf16x2(float x0, float x1) {
    uint32_t r;
    asm("cvt.rn.bf16x2.f32 %0, %1, %2;" : "=r"(r) : "f"(x1), "f"(x0));
    return r;
}

// m16n8k16 bf16 MMA, f32 accumulate (sm_80+ baseline PTX)
__device__ __forceinline__ void mma16(float* c, uint4 a, uint32_t b0, uint32_t b1) {
    asm volatile(
        "mma.sync.aligned.m16n8k16.row.col.f32.bf16.bf16.f32 "
        "{%0,%1,%2,%3}, {%4,%5,%6,%7}, {%8,%9}, {%0,%1,%2,%3};"
        : "+f"(c[0]), "+f"(c[1]), "+f"(c[2]), "+f"(c[3])
        : "r"(a.x), "r"(a.y), "r"(a.z), "r"(a.w), "r"(b0), "r"(b1));
}

// ======================= CSR build (by dst) ==============================
__global__ void hist_kernel(const int* __restrict__ dst, int* __restrict__ deg)
{
    int e = blockIdx.x * blockDim.x + threadIdx.x;
    if (e < N_EDGES) atomicAdd(deg + __ldg(dst + e), 1);
}

__global__ void scan1_kernel(const int* __restrict__ deg,
                             int* __restrict__ incl, int* __restrict__ bsum)
{
    __shared__ int s[SCAN_BLK];
    int gid = blockIdx.x * SCAN_BLK + threadIdx.x;
    int v = (gid < N_NODES) ? deg[gid] : 0;
    s[threadIdx.x] = v;
    __syncthreads();
    #pragma unroll
    for (int off = 1; off < SCAN_BLK; off <<= 1) {
        int t = (threadIdx.x >= off) ? s[threadIdx.x - off] : 0;
        __syncthreads();
        s[threadIdx.x] += t;
        __syncthreads();
    }
    incl[gid] = s[threadIdx.x];
    if (threadIdx.x == SCAN_BLK - 1) bsum[blockIdx.x] = s[threadIdx.x];
}

__global__ void scan2_kernel(const int* __restrict__ bsum, int* __restrict__ boff)
{
    __shared__ int s[512];
    int t = threadIdx.x;
    s[t] = (t < N_SCAN_BLOCKS) ? bsum[t] : 0;
    __syncthreads();
    #pragma unroll
    for (int off = 1; off < 512; off <<= 1) {
        int v = (t >= off) ? s[t - off] : 0;
        __syncthreads();
        s[t] += v;
        __syncthreads();
    }
    if (t < N_SCAN_BLOCKS) boff[t] = s[t] - bsum[t];
}

__global__ void scan3_kernel(const int* __restrict__ deg,
                             const int* __restrict__ incl,
                             const int* __restrict__ boff,
                             int* __restrict__ rowptr)
{
    int i = blockIdx.x * blockDim.x + threadIdx.x;
    if (i < N_NODES)
        rowptr[i] = incl[i] - deg[i] + boff[i / SCAN_BLK];
    if (i == 0) rowptr[N_NODES] = N_EDGES;
}

__global__ void fill_kernel(const int* __restrict__ src,
                            const int* __restrict__ dst,
                            const float* __restrict__ ew,
                            const int* __restrict__ rowptr,
                            int* __restrict__ cursor,
                            int* __restrict__ csr_src,
                            float* __restrict__ csr_ew)
{
    int e = blockIdx.x * blockDim.x + threadIdx.x;
    if (e >= N_EDGES) return;
    int d = __ldg(dst + e);
    int pos = atomicAdd(cursor + d, 1);
    int idx = __ldg(rowptr + d) + pos;
    csr_src[idx] = __ldg(src + e);
    csr_ew[idx]  = __ldg(ew + e);
}

// ---------------- fold BN params (+rel bias) into scale/shift -------------
__global__ void bn_fold_kernel(const float* __restrict__ br0, const float* __restrict__ g0,
                               const float* __restrict__ b0,  const float* __restrict__ m0,
                               const float* __restrict__ v0,
                               const float* __restrict__ br1, const float* __restrict__ g1,
                               const float* __restrict__ b1,  const float* __restrict__ m1,
                               const float* __restrict__ v1,
                               const float* __restrict__ br2, const float* __restrict__ g2,
                               const float* __restrict__ b2,  const float* __restrict__ m2,
                               const float* __restrict__ v2)
{
    int j = threadIdx.x;
    int l = blockIdx.x;
    const float* br = (l == 0) ? br0 : (l == 1) ? br1 : br2;
    const float* g  = (l == 0) ? g0  : (l == 1) ? g1  : g2;
    const float* b  = (l == 0) ? b0  : (l == 1) ? b1  : b2;
    const float* m  = (l == 0) ? m0  : (l == 1) ? m1  : m2;
    const float* v  = (l == 0) ? v0  : (l == 1) ? v1  : v2;
    float s = g[j] * rsqrtf(v[j] + EPS);
    g_scale[l][j] = s;
    g_shift[l][j] = (br[j] - m[j]) * s + b[j];
}

// -------- prep: bf16-split weights into m16n8k16 fragment order ----------
// word (hilo, ks, ng, lane, idx): nt=idx>>1, breg=idx&1
//   k0 = ks*16 + (lane&3)*2 + breg*8 (covers k0, k0+1); n = ng*64 + nt*8 + (lane>>2)
__global__ void prep_weights_kernel(const float* __restrict__ Wr0, const float* __restrict__ Wo0,
                                    const float* __restrict__ Wr1, const float* __restrict__ Wo1,
                                    const float* __restrict__ Wr2, const float* __restrict__ Wo2)
{
    int id = blockIdx.x * blockDim.x + threadIdx.x;
    int total = 16384 + 32768 + 32768;
    if (id >= total) return;
    int KS16, base, rem;
    const float *Wr, *Wo;
    if (id < 16384)          { KS16 = 4; base = 0;     rem = id;          Wr = Wr0; Wo = Wo0; }
    else if (id < 49152)     { KS16 = 8; base = 16384; rem = id - 16384;  Wr = Wr1; Wo = Wo1; }
    else                     { KS16 = 8; base = 49152; rem = id - 49152;  Wr = Wr2; Wo = Wo2; }
    int idx  = rem & 15;
    int lane = (rem >> 4) & 31;
    int ng   = (rem >> 9) & 3;
    int t    = rem >> 11;
    int ks   = t % KS16;
    int hilo = t / KS16;
    int nt = idx >> 1, breg = idx & 1;
    int k0 = ks * 16 + (lane & 3) * 2 + breg * 8;
    int n  = ng * 64 + nt * 8 + (lane >> 2);
    int jj = n & 127;
    const float* W = (n < 128) ? Wr : Wo;
    float w0 = __ldg(W + (k0 + 0) * 128 + jj);
    float w1 = __ldg(W + (k0 + 1) * 128 + jj);
    uint32_t hw = bf16x2(w0, w1);
    uint32_t out = hw;
    if (hilo) {
        float h0 = __uint_as_float(hw << 16);
        float h1 = __uint_as_float(hw & 0xffff0000u);
        out = bf16x2(w0 - h0, w1 - h1);
    }
    g_Bf[base + rem] = out;
}

// ====== tensor-core dual GEMM via mma.sync bf16 (3-term split) ============
// CTA: 64-node tile x 256 cols, 8 warps (256 thr), 2 CTAs/SM co-resident.
// warp (mg=w>>2 in {0,1}, ng=w&3): rows [mg*32,+32), cols [ng*64,+64).
// smem: raw 64x(K+4) floats, then A-frag (K*256 bytes) as packed bf16 words:
// [mg][ks16][chunk(4: mt*2+hilo)][lane][4] (LDS.128 conflict-free).
template <int KS16>
__global__ void __launch_bounds__(256, 2)
gemm_mma_kernel(const float* __restrict__ h,
                const uint32_t* __restrict__ Bf,
                float* __restrict__ hr,
                float* __restrict__ ho)
{
    constexpr int K = KS16 * 16;
    extern __shared__ float smem[];
    float*    sRaw  = smem;                                   // 64*(K+4) floats
    uint32_t* fragU = reinterpret_cast<uint32_t*>(smem + 64 * (K + 4));

    const int tid  = threadIdx.x;
    const int w    = tid >> 5;
    const int lane = tid & 31;
    const int mg   = w >> 2;                  // 0..1
    const int ng   = w & 3;                   // 0..3
    const int n0   = blockIdx.x * 64;

    // ---- stage raw activation tile (coalesced uint4) ----
    for (int i = tid; i < 16 * K; i += 256) {       // 16*K uint4 = 64*K floats
        int row = i / (K / 4);
        int c   = i % (K / 4);
        uint4 v = make_uint4(0u, 0u, 0u, 0u);
        if (n0 + row < N_NODES)
            v = *reinterpret_cast<const uint4*>(h + (size_t)(n0 + row) * K + c * 4);
        *reinterpret_cast<uint4*>(&sRaw[row * (K + 4) + c * 4]) = v;
    }
    __syncthreads();

    // ---- convert to bf16 hi/lo A fragments (warp handles mg, ks = ng+4j) ----
    for (int j = 0; j < KS16 / 4; j++) {
        int ks = ng + 4 * j;
        int cbase = (mg * KS16 + ks) * 4;
        #pragma unroll
        for (int mt = 0; mt < 2; mt++) {
            #pragma unroll
            for (int r = 0; r < 4; r++) {
                int row = mg * 32 + mt * 16 + (lane >> 2) + (r & 1) * 8;
                int k0  = ks * 16 + (lane & 3) * 2 + ((r >> 1) & 1) * 8;
                float x0 = sRaw[row * (K + 4) + k0];
                float x1 = sRaw[row * (K + 4) + k0 + 1];
                uint32_t hw = bf16x2(x0, x1);
                float h0 = __uint_as_float(hw << 16);
                float h1 = __uint_as_float(hw & 0xffff0000u);
                uint32_t lw = bf16x2(x0 - h0, x1 - h1);
                fragU[((cbase + mt * 2 + 0) * 32 + lane) * 4 + r] = hw;
                fragU[((cbase + mt * 2 + 1) * 32 + lane) * 4 + r] = lw;
            }
        }
    }
    __syncthreads();

    // ---- MMA mainloop ----
    float acc[2][8][4];
    #pragma unroll
    for (int mt = 0; mt < 2; mt++)
        #pragma unroll
        for (int nt = 0; nt < 8; nt++)
            #pragma unroll
            for (int r = 0; r < 4; r++) acc[mt][nt][r] = 0.f;

    const uint4* fragQ = reinterpret_cast<const uint4*>(fragU);
    const uint4* BfQ   = reinterpret_cast<const uint4*>(Bf);

    for (int ks = 0; ks < KS16; ks++) {
        const uint4* aB = fragQ + ((mg * KS16 + ks) * 4) * 32 + lane;
        uint4 a0h = aB[0 * 32];
        uint4 a0l = aB[1 * 32];
        uint4 a1h = aB[2 * 32];
        uint4 a1l = aB[3 * 32];

        const uint4* bHiB = BfQ + (((0 * KS16 + ks) * 4 + ng) * 32 + lane) * 4;
        uint4 bh0 = __ldg(bHiB + 0);
        uint4 bh1 = __ldg(bHiB + 1);
        uint4 bh2 = __ldg(bHiB + 2);
        uint4 bh3 = __ldg(bHiB + 3);

        // pass hh + lh (share Bhi)
        mma16(acc[0][0], a0h, bh0.x, bh0.y);  mma16(acc[0][1], a0h, bh0.z, bh0.w);
        mma16(acc[0][2], a0h, bh1.x, bh1.y);  mma16(acc[0][3], a0h, bh1.z, bh1.w);
        mma16(acc[0][4], a0h, bh2.x, bh2.y);  mma16(acc[0][5], a0h, bh2.z, bh2.w);
        mma16(acc[0][6], a0h, bh3.x, bh3.y);  mma16(acc[0][7], a0h, bh3.z, bh3.w);
        mma16(acc[1][0], a1h, bh0.x, bh0.y);  mma16(acc[1][1], a1h, bh0.z, bh0.w);
        mma16(acc[1][2], a1h, bh1.x, bh1.y);  mma16(acc[1][3], a1h, bh1.z, bh1.w);
        mma16(acc[1][4], a1h, bh2.x, bh2.y);  mma16(acc[1][5], a1h, bh2.z, bh2.w);
        mma16(acc[1][6], a1h, bh3.x, bh3.y);  mma16(acc[1][7], a1h, bh3.z, bh3.w);

        mma16(acc[0][0], a0l, bh0.x, bh0.y);  mma16(acc[0][1], a0l, bh0.z, bh0.w);
        mma16(acc[0][2], a0l, bh1.x, bh1.y);  mma16(acc[0][3], a0l, bh1.z, bh1.w);
        mma16(acc[0][4], a0l, bh2.x, bh2.y);  mma16(acc[0][5], a0l, bh2.z, bh2.w);
        mma16(acc[0][6], a0l, bh3.x, bh3.y);  mma16(acc[0][7], a0l, bh3.z, bh3.w);
        mma16(acc[1][0], a1l, bh0.x, bh0.y);  mma16(acc[1][1], a1l, bh0.z, bh0.w);
        mma16(acc[1][2], a1l, bh1.x, bh1.y);  mma16(acc[1][3], a1l, bh1.z, bh1.w);
        mma16(acc[1][4], a1l, bh2.x, bh2.y);  mma16(acc[1][5], a1l, bh2.z, bh2.w);
        mma16(acc[1][6], a1l, bh3.x, bh3.y);  mma16(acc[1][7], a1l, bh3.z, bh3.w);

        const uint4* bLoB = BfQ + (((1 * KS16 + ks) * 4 + ng) * 32 + lane) * 4;
        uint4 bl0 = __ldg(bLoB + 0);
        uint4 bl1 = __ldg(bLoB + 1);
        uint4 bl2 = __ldg(bLoB + 2);
        uint4 bl3 = __ldg(bLoB + 3);

        // pass hl
        mma16(acc[0][0], a0h, bl0.x, bl0.y);  mma16(acc[0][1], a0h, bl0.z, bl0.w);
        mma16(acc[0][2], a0h, bl1.x, bl1.y);  mma16(acc[0][3], a0h, bl1.z, bl1.w);
        mma16(acc[0][4], a0h, bl2.x, bl2.y);  mma16(acc[0][5], a0h, bl2.z, bl2.w);
        mma16(acc[0][6], a0h, bl3.x, bl3.y);  mma16(acc[0][7], a0h, bl3.z, bl3.w);
        mma16(acc[1][0], a1h, bl0.x, bl0.y);  mma16(acc[1][1], a1h, bl0.z, bl0.w);
        mma16(acc[1][2], a1h, bl1.x, bl1.y);  mma16(acc[1][3], a1h, bl1.z, bl1.w);
        mma16(acc[1][4], a1h, bl2.x, bl2.y);  mma16(acc[1][5], a1h, bl2.z, bl2.w);
        mma16(acc[1][6], a1h, bl3.x, bl3.y);  mma16(acc[1][7], a1h, bl3.z, bl3.w);
    }

    // ---- epilogue: acc -> hr / ho ----
    float* dst = (ng < 2) ? hr : ho;
    const int colbase = (ng & 1) * 64;
    #pragma unroll
    for (int mt = 0; mt < 2; mt++) {
        int row = n0 + mg * 32 + mt * 16 + (lane >> 2);
        #pragma unroll
        for (int nt = 0; nt < 8; nt++) {
            int col = colbase + nt * 8 + 2 * (lane & 3);
            if (row < N_NODES)
                *reinterpret_cast<float2*>(dst + (size_t)row * 128 + col) =
                    make_float2(acc[mt][nt][0], acc[mt][nt][1]);
            if (row + 8 < N_NODES)
                *reinterpret_cast<float2*>(dst + (size_t)(row + 8) * 128 + col) =
                    make_float2(acc[mt][nt][2], acc[mt][nt][3]);
        }
    }
}

#define GEMM_SMEM(K) (64 * ((K) + 4) * 4 + (K) * 256)

// === fused gather + root + BN + ReLU:  out = relu((Σ ew*hr[src] + ho)*s + t)
__global__ void gather_fused_kernel(const float* __restrict__ hr,
                                    const float* __restrict__ ho,
                                    const int* __restrict__ rowptr,
                                    const int* __restrict__ csr_src,
                                    const float* __restrict__ csr_ew,
                                    const float* __restrict__ scale,
                                    const float* __restrict__ shift,
                                    float* __restrict__ out)
{
    int node = (blockIdx.x * blockDim.x + threadIdx.x) >> 5;
    if (node >= N_NODES) return;
    int lane = threadIdx.x & 31;
    int beg = __ldg(rowptr + node);
    int end = __ldg(rowptr + node + 1);

    const float4* hr4 = reinterpret_cast<const float4*>(hr);
    float4 acc = *(reinterpret_cast<const float4*>(ho + (size_t)node * 128) + lane);

    int i = beg;
    for (; i + 3 < end; i += 4) {
        int   s0 = __ldg(csr_src + i);
        int   s1 = __ldg(csr_src + i + 1);
        int   s2 = __ldg(csr_src + i + 2);
        int   s3 = __ldg(csr_src + i + 3);
        float e0 = __ldg(csr_ew + i);
        float e1 = __ldg(csr_ew + i + 1);
        float e2 = __ldg(csr_ew + i + 2);
        float e3 = __ldg(csr_ew + i + 3);
        float4 v0 = hr4[(size_t)s0 * 32 + lane];
        float4 v1 = hr4[(size_t)s1 * 32 + lane];
        float4 v2 = hr4[(size_t)s2 * 32 + lane];
        float4 v3 = hr4[(size_t)s3 * 32 + lane];
        acc.x = fmaf(v0.x, e0, acc.x); acc.y = fmaf(v0.y, e0, acc.y);
        acc.z = fmaf(v0.z, e0, acc.z); acc.w = fmaf(v0.w, e0, acc.w);
        acc.x = fmaf(v1.x, e1, acc.x); acc.y = fmaf(v1.y, e1, acc.y);
        acc.z = fmaf(v1.z, e1, acc.z); acc.w = fmaf(v1.w, e1, acc.w);
        acc.x = fmaf(v2.x, e2, acc.x); acc.y = fmaf(v2.y, e2, acc.y);
        acc.z = fmaf(v2.z, e2, acc.z); acc.w = fmaf(v2.w, e2, acc.w);
        acc.x = fmaf(v3.x, e3, acc.x); acc.y = fmaf(v3.y, e3, acc.y);
        acc.z = fmaf(v3.z, e3, acc.z); acc.w = fmaf(v3.w, e3, acc.w);
    }
    for (; i < end; i++) {
        int   s0 = __ldg(csr_src + i);
        float e0 = __ldg(csr_ew + i);
        float4 v0 = hr4[(size_t)s0 * 32 + lane];
        acc.x = fmaf(v0.x, e0, acc.x); acc.y = fmaf(v0.y, e0, acc.y);
        acc.z = fmaf(v0.z, e0, acc.z); acc.w = fmaf(v0.w, e0, acc.w);
    }

    float4 sc = *(reinterpret_cast<const float4*>(scale) + lane);
    float4 sh = *(reinterpret_cast<const float4*>(shift) + lane);
    float4 res;
    res.x = fmaxf(fmaf(acc.x, sc.x, sh.x), 0.f);
    res.y = fmaxf(fmaf(acc.y, sc.y, sh.y), 0.f);
    res.z = fmaxf(fmaf(acc.z, sc.z, sh.z), 0.f);
    res.w = fmaxf(fmaf(acc.w, sc.w, sh.w), 0.f);
    *(reinterpret_cast<float4*>(out + (size_t)node * 128) + lane) = res;
}

// ------------- fused mean-pool + head (block per graph) ------------------
__global__ void pool_head_kernel(const float* __restrict__ h,
                                 const int* __restrict__ batch,
                                 const float* __restrict__ W1,
                                 const float* __restrict__ b1,
                                 const float* __restrict__ W2,
                                 const float* __restrict__ b2,
                                 float* __restrict__ out)
{
    __shared__ float sp[HIDDEN];
    __shared__ float sred[128];
    __shared__ int srange[2];
    const int g = blockIdx.x;
    const int t = threadIdx.x;

    if (t < 2) {
        int key = g + t;
        int lo = 0, hi = N_NODES;
        while (lo < hi) {
            int mid = (lo + hi) >> 1;
            if (__ldg(batch + mid) < key) lo = mid + 1; else hi = mid;
        }
        srange[t] = lo;
    }
    __syncthreads();
    const int start = srange[0];
    const int end   = srange[1];

    float sum = 0.f;
    for (int n = start; n < end; n++)
        sum += h[(size_t)n * HIDDEN + t];
    float inv = 1.0f / fmaxf((float)(end - start), 1.0f);
    sp[t] = sum * inv;
    __syncthreads();

    float val = 0.f;
    if (t < 64) {
        float acc = __ldg(b1 + t);
        #pragma unroll 8
        for (int k = 0; k < HIDDEN; k++)
            acc = fmaf(sp[k], __ldg(W1 + k * 64 + t), acc);
        val = fmaxf(acc, 0.f) * __ldg(W2 + t);
    }
    sred[t] = val;
    __syncthreads();
    for (int s = 64; s > 0; s >>= 1) {
        if (t < s) sred[t] += sred[t + s];
        __syncthreads();
    }
    if (t == 0) out[g] = sred[0] + __ldg(b2);
}

// -------------------------------------------------------------------------
extern "C" void kernel_launch(void* const* d_in, const int* in_sizes, int n_in,
                              void* d_out, int out_size)
{
    (void)in_sizes; (void)n_in; (void)out_size;
    const float* x     = (const float*)d_in[0];
    const int*   ei    = (const int*)  d_in[1];
    const float* ea    = (const float*)d_in[2];
    const int*   batch = (const int*)  d_in[3];
    const float* P[21];
    for (int i = 0; i < 21; i++) P[i] = (const float*)d_in[4 + i];
    const float* head_w1 = (const float*)d_in[25];
    const float* head_b1 = (const float*)d_in[26];
    const float* head_w2 = (const float*)d_in[27];
    const float* head_b2 = (const float*)d_in[28];
    float* out = (float*)d_out;

    float *hr, *ho, *ha, *hb, *scale, *shift;
    uint32_t* Bf;
    int *deg, *incl, *bsum, *boff, *rowptr, *cursor, *csr_src;
    float *csr_ew;
    cudaGetSymbolAddress((void**)&hr,      g_hr);
    cudaGetSymbolAddress((void**)&ho,      g_ho);
    cudaGetSymbolAddress((void**)&ha,      g_ha);
    cudaGetSymbolAddress((void**)&hb,      g_hb);
    cudaGetSymbolAddress((void**)&scale,   g_scale);
    cudaGetSymbolAddress((void**)&shift,   g_shift);
    cudaGetSymbolAddress((void**)&Bf,      g_Bf);
    cudaGetSymbolAddress((void**)&deg,     g_deg);
    cudaGetSymbolAddress((void**)&incl,    g_incl);
    cudaGetSymbolAddress((void**)&bsum,    g_bsum);
    cudaGetSymbolAddress((void**)&boff,    g_boff);
    cudaGetSymbolAddress((void**)&rowptr,  g_rowptr);
    cudaGetSymbolAddress((void**)&cursor,  g_cursor);
    cudaGetSymbolAddress((void**)&csr_src, g_csr_src);
    cudaGetSymbolAddress((void**)&csr_ew,  g_csr_ew);

    cudaFuncSetAttribute(gemm_mma_kernel<4>,
                         cudaFuncAttributeMaxDynamicSharedMemorySize, GEMM_SMEM(64));
    cudaFuncSetAttribute(gemm_mma_kernel<8>,
                         cudaFuncAttributeMaxDynamicSharedMemorySize, GEMM_SMEM(128));

    const int* src = ei;
    const int* dst = ei + N_EDGES;

    const int gather_blocks = (N_NODES * 32 + 255) / 256;

    // Launch order: 6th launch (ncu -s 5 -c 1) is gemm layer 0.
    prep_weights_kernel<<<(16384 + 32768 + 32768 + 255) / 256, 256>>>(
        P[0], P[2], P[7], P[9], P[14], P[16]);                       // 1
    cudaMemsetAsync(deg,    0, N_NODES * sizeof(int), 0);            // 2
    cudaMemsetAsync(cursor, 0, N_NODES * sizeof(int), 0);            // 3
    hist_kernel<<<(N_EDGES + 255) / 256, 256>>>(dst, deg);           // 4
    scan1_kernel<<<N_SCAN_BLOCKS, SCAN_BLK>>>(deg, incl, bsum);      // 5
    gemm_mma_kernel<4><<<N_TILES64, 256, GEMM_SMEM(64)>>>(x, Bf, hr, ho); // 6 (profiled)
    scan2_kernel<<<1, 512>>>(bsum, boff);                            // 7
    scan3_kernel<<<(N_NODES + 255) / 256, 256>>>(deg, incl, boff, rowptr); // 8
    fill_kernel<<<(N_EDGES + 255) / 256, 256>>>(src, dst, ea, rowptr, cursor,
                                                csr_src, csr_ew);    // 9
    bn_fold_kernel<<<3, 128>>>(P[1], P[3], P[4], P[5], P[6],
                               P[8], P[10], P[11], P[12], P[13],
                               P[15], P[17], P[18], P[19], P[20]);   // 10

    // ---- Layer 0 gather ----
    gather_fused_kernel<<<gather_blocks, 256>>>(hr, ho, rowptr, csr_src, csr_ew,
                                                scale + 0 * HIDDEN, shift + 0 * HIDDEN, ha);

    // ---- Layer 1 ----
    gemm_mma_kernel<8><<<N_TILES64, 256, GEMM_SMEM(128)>>>(ha, Bf + 16384, hr, ho);
    gather_fused_kernel<<<gather_blocks, 256>>>(hr, ho, rowptr, csr_src, csr_ew,
                                                scale + 1 * HIDDEN, shift + 1 * HIDDEN, hb);

    // ---- Layer 2 ----
    gemm_mma_kernel<8><<<N_TILES64, 256, GEMM_SMEM(128)>>>(hb, Bf + 49152, hr, ho);
    gather_fused_kernel<<<gather_blocks, 256>>>(hr, ho, rowptr, csr_src, csr_ew,
                                                scale + 2 * HIDDEN, shift + 2 * HIDDEN, ha);

    // ---- Fused mean pool + head ----
    pool_head_kernel<<<N_GRAPHS, 128>>>(ha, batch, head_w1, head_b1,
                                        head_w2, head_b2, out);
}

// round 10
// speedup vs baseline: 1.6597x; 1.1791x over previous
#include <cuda_runtime.h>
#include <cstdint>
#include <cstddef>

#define N_NODES 100000
#define N_EDGES 1600000
#define F_IN    64
#define HIDDEN  128
#define N_GRAPHS 1024
#define EPS 1e-5f

#define SCAN_BLK 256
#define N_SCAN_BLOCKS ((N_NODES + SCAN_BLK - 1) / SCAN_BLK)   // 391
#define N_TILES64 ((N_NODES + 63) / 64)                        // 1563

// ---------------- static scratch (no allocation allowed) ----------------
__device__ float g_hr[(size_t)N_NODES * HIDDEN];
__device__ float g_ho[(size_t)N_NODES * HIDDEN];
__device__ float g_ha[(size_t)N_NODES * HIDDEN];
__device__ float g_hb[(size_t)N_NODES * HIDDEN];

__device__ float g_scale[3][HIDDEN];
__device__ float g_shift[3][HIDDEN];

// bf16-split B fragments, QUAD-MAJOR coalesced layout (packed bf16x2 words):
// word index = ((((hilo*KS16+ks)*4 + ng)*4 + q)*32 + lane)*4 + w,  idx = 4q+w
// layer0 (K=64): 16384 words, layer1/2 (K=128): 32768 words each
__device__ __align__(16) uint32_t g_Bf[16384 + 32768 + 32768];

__device__ int   g_deg[N_NODES];
__device__ int   g_incl[N_SCAN_BLOCKS * SCAN_BLK];
__device__ int   g_bsum[N_SCAN_BLOCKS];
__device__ int   g_boff[N_SCAN_BLOCKS];
__device__ int   g_rowptr[N_NODES + 1];
__device__ int   g_cursor[N_NODES];
__device__ int   g_csr_src[N_EDGES];
__device__ float g_csr_ew[N_EDGES];

// pack two floats to bf16x2 word: low half = x0, high half = x1
__device__ __forceinline__ uint32_t bf16x2(float x0, float x1) {
    uint32_t r;
    asm("cvt.rn.bf16x2.f32 %0, %1, %2;" : "=r"(r) : "f"(x1), "f"(x0));
    return r;
}

// m16n8k16 bf16 MMA, f32 accumulate (sm_80+ baseline PTX)
__device__ __forceinline__ void mma16(float* c, uint4 a, uint32_t b0, uint32_t b1) {
    asm volatile(
        "mma.sync.aligned.m16n8k16.row.col.f32.bf16.bf16.f32 "
        "{%0,%1,%2,%3}, {%4,%5,%6,%7}, {%8,%9}, {%0,%1,%2,%3};"
        : "+f"(c[0]), "+f"(c[1]), "+f"(c[2]), "+f"(c[3])
        : "r"(a.x), "r"(a.y), "r"(a.z), "r"(a.w), "r"(b0), "r"(b1));
}

// ======================= CSR build (by dst) ==============================
__global__ void hist_kernel(const int* __restrict__ dst, int* __restrict__ deg)
{
    int e = blockIdx.x * blockDim.x + threadIdx.x;
    if (e < N_EDGES) atomicAdd(deg + __ldg(dst + e), 1);
}

__global__ void scan1_kernel(const int* __restrict__ deg,
                             int* __restrict__ incl, int* __restrict__ bsum)
{
    __shared__ int s[SCAN_BLK];
    int gid = blockIdx.x * SCAN_BLK + threadIdx.x;
    int v = (gid < N_NODES) ? deg[gid] : 0;
    s[threadIdx.x] = v;
    __syncthreads();
    #pragma unroll
    for (int off = 1; off < SCAN_BLK; off <<= 1) {
        int t = (threadIdx.x >= off) ? s[threadIdx.x - off] : 0;
        __syncthreads();
        s[threadIdx.x] += t;
        __syncthreads();
    }
    incl[gid] = s[threadIdx.x];
    if (threadIdx.x == SCAN_BLK - 1) bsum[blockIdx.x] = s[threadIdx.x];
}

__global__ void scan2_kernel(const int* __restrict__ bsum, int* __restrict__ boff)
{
    __shared__ int s[512];
    int t = threadIdx.x;
    s[t] = (t < N_SCAN_BLOCKS) ? bsum[t] : 0;
    __syncthreads();
    #pragma unroll
    for (int off = 1; off < 512; off <<= 1) {
        int v = (t >= off) ? s[t - off] : 0;
        __syncthreads();
        s[t] += v;
        __syncthreads();
    }
    if (t < N_SCAN_BLOCKS) boff[t] = s[t] - bsum[t];
}

__global__ void scan3_kernel(const int* __restrict__ deg,
                             const int* __restrict__ incl,
                             const int* __restrict__ boff,
                             int* __restrict__ rowptr)
{
    int i = blockIdx.x * blockDim.x + threadIdx.x;
    if (i < N_NODES)
        rowptr[i] = incl[i] - deg[i] + boff[i / SCAN_BLK];
    if (i == 0) rowptr[N_NODES] = N_EDGES;
}

__global__ void fill_kernel(const int* __restrict__ src,
                            const int* __restrict__ dst,
                            const float* __restrict__ ew,
                            const int* __restrict__ rowptr,
                            int* __restrict__ cursor,
                            int* __restrict__ csr_src,
                            float* __restrict__ csr_ew)
{
    int e = blockIdx.x * blockDim.x + threadIdx.x;
    if (e >= N_EDGES) return;
    int d = __ldg(dst + e);
    int pos = atomicAdd(cursor + d, 1);
    int idx = __ldg(rowptr + d) + pos;
    csr_src[idx] = __ldg(src + e);
    csr_ew[idx]  = __ldg(ew + e);
}

// ---------------- fold BN params (+rel bias) into scale/shift -------------
__global__ void bn_fold_kernel(const float* __restrict__ br0, const float* __restrict__ g0,
                               const float* __restrict__ b0,  const float* __restrict__ m0,
                               const float* __restrict__ v0,
                               const float* __restrict__ br1, const float* __restrict__ g1,
                               const float* __restrict__ b1,  const float* __restrict__ m1,
                               const float* __restrict__ v1,
                               const float* __restrict__ br2, const float* __restrict__ g2,
                               const float* __restrict__ b2,  const float* __restrict__ m2,
                               const float* __restrict__ v2)
{
    int j = threadIdx.x;
    int l = blockIdx.x;
    const float* br = (l == 0) ? br0 : (l == 1) ? br1 : br2;
    const float* g  = (l == 0) ? g0  : (l == 1) ? g1  : g2;
    const float* b  = (l == 0) ? b0  : (l == 1) ? b1  : b2;
    const float* m  = (l == 0) ? m0  : (l == 1) ? m1  : m2;
    const float* v  = (l == 0) ? v0  : (l == 1) ? v1  : v2;
    float s = g[j] * rsqrtf(v[j] + EPS);
    g_scale[l][j] = s;
    g_shift[l][j] = (br[j] - m[j]) * s + b[j];
}

// -------- prep: bf16-split weights into QUAD-MAJOR fragment order --------
// word (hilo, ks, ng, q, lane, w): idx = 4q+w, nt=idx>>1, breg=idx&1
//   k0 = ks*16 + (lane&3)*2 + breg*8 (covers k0, k0+1); n = ng*64 + nt*8 + (lane>>2)
__global__ void prep_weights_kernel(const float* __restrict__ Wr0, const float* __restrict__ Wo0,
                                    const float* __restrict__ Wr1, const float* __restrict__ Wo1,
                                    const float* __restrict__ Wr2, const float* __restrict__ Wo2)
{
    int id = blockIdx.x * blockDim.x + threadIdx.x;
    int total = 16384 + 32768 + 32768;
    if (id >= total) return;
    int KS16, base, rem;
    const float *Wr, *Wo;
    if (id < 16384)          { KS16 = 4; base = 0;     rem = id;          Wr = Wr0; Wo = Wo0; }
    else if (id < 49152)     { KS16 = 8; base = 16384; rem = id - 16384;  Wr = Wr1; Wo = Wo1; }
    else                     { KS16 = 8; base = 49152; rem = id - 49152;  Wr = Wr2; Wo = Wo2; }
    int w    = rem & 3;
    int lane = (rem >> 2) & 31;
    int q    = (rem >> 7) & 3;
    int ng   = (rem >> 9) & 3;
    int t    = rem >> 11;
    int ks   = t % KS16;
    int hilo = t / KS16;
    int idx  = q * 4 + w;
    int nt = idx >> 1, breg = idx & 1;
    int k0 = ks * 16 + (lane & 3) * 2 + breg * 8;
    int n  = ng * 64 + nt * 8 + (lane >> 2);
    int jj = n & 127;
    const float* W = (n < 128) ? Wr : Wo;
    float w0 = __ldg(W + (k0 + 0) * 128 + jj);
    float w1 = __ldg(W + (k0 + 1) * 128 + jj);
    uint32_t hw = bf16x2(w0, w1);
    uint32_t out = hw;
    if (hilo) {
        float h0 = __uint_as_float(hw << 16);
        float h1 = __uint_as_float(hw & 0xffff0000u);
        out = bf16x2(w0 - h0, w1 - h1);
    }
    g_Bf[base + rem] = out;
}

// ====== tensor-core dual GEMM via mma.sync bf16 (3-term split) ============
// CTA: 64-node tile x 256 cols, 8 warps (256 thr), 2 CTAs/SM co-resident.
// warp (mg=w>>2 in {0,1}, ng=w&3): rows [mg*32,+32), cols [ng*64,+64).
// smem: raw 64x(K+4) floats, then A-frag (K*256 bytes) as packed bf16 words:
// [mg][ks16][chunk(4: mt*2+hilo)][lane][4] (LDS.128 conflict-free).
template <int KS16>
__global__ void __launch_bounds__(256, 2)
gemm_mma_kernel(const float* __restrict__ h,
                const uint32_t* __restrict__ Bf,
                float* __restrict__ hr,
                float* __restrict__ ho)
{
    constexpr int K = KS16 * 16;
    extern __shared__ float smem[];
    float*    sRaw  = smem;                                   // 64*(K+4) floats
    uint32_t* fragU = reinterpret_cast<uint32_t*>(smem + 64 * (K + 4));

    const int tid  = threadIdx.x;
    const int w    = tid >> 5;
    const int lane = tid & 31;
    const int mg   = w >> 2;                  // 0..1
    const int ng   = w & 3;                   // 0..3
    const int n0   = blockIdx.x * 64;

    // ---- stage raw activation tile (coalesced uint4) ----
    for (int i = tid; i < 16 * K; i += 256) {       // 16*K uint4 = 64*K floats
        int row = i / (K / 4);
        int c   = i % (K / 4);
        uint4 v = make_uint4(0u, 0u, 0u, 0u);
        if (n0 + row < N_NODES)
            v = *reinterpret_cast<const uint4*>(h + (size_t)(n0 + row) * K + c * 4);
        *reinterpret_cast<uint4*>(&sRaw[row * (K + 4) + c * 4]) = v;
    }
    __syncthreads();

    // ---- convert to bf16 hi/lo A fragments (warp handles mg, ks = ng+4j) ----
    // packed STS.128: r = 0..3 are contiguous words per (chunk, lane)
    for (int j = 0; j < KS16 / 4; j++) {
        int ks = ng + 4 * j;
        int cbase = (mg * KS16 + ks) * 4;
        #pragma unroll
        for (int mt = 0; mt < 2; mt++) {
            uint32_t hwv[4], lwv[4];
            #pragma unroll
            for (int r = 0; r < 4; r++) {
                int row = mg * 32 + mt * 16 + (lane >> 2) + (r & 1) * 8;
                int k0  = ks * 16 + (lane & 3) * 2 + ((r >> 1) & 1) * 8;
                float x0 = sRaw[row * (K + 4) + k0];
                float x1 = sRaw[row * (K + 4) + k0 + 1];
                uint32_t hw = bf16x2(x0, x1);
                float h0 = __uint_as_float(hw << 16);
                float h1 = __uint_as_float(hw & 0xffff0000u);
                hwv[r] = hw;
                lwv[r] = bf16x2(x0 - h0, x1 - h1);
            }
            *reinterpret_cast<uint4*>(&fragU[((cbase + mt * 2 + 0) * 32 + lane) * 4]) =
                make_uint4(hwv[0], hwv[1], hwv[2], hwv[3]);
            *reinterpret_cast<uint4*>(&fragU[((cbase + mt * 2 + 1) * 32 + lane) * 4]) =
                make_uint4(lwv[0], lwv[1], lwv[2], lwv[3]);
        }
    }
    __syncthreads();

    // ---- MMA mainloop ----
    float acc[2][8][4];
    #pragma unroll
    for (int mt = 0; mt < 2; mt++)
        #pragma unroll
        for (int nt = 0; nt < 8; nt++)
            #pragma unroll
            for (int r = 0; r < 4; r++) acc[mt][nt][r] = 0.f;

    const uint4* fragQ = reinterpret_cast<const uint4*>(fragU);
    const uint4* BfQ   = reinterpret_cast<const uint4*>(Bf);

    for (int ks = 0; ks < KS16; ks++) {
        const uint4* aB = fragQ + ((mg * KS16 + ks) * 4) * 32 + lane;
        uint4 a0h = aB[0 * 32];
        uint4 a0l = aB[1 * 32];
        uint4 a1h = aB[2 * 32];
        uint4 a1l = aB[3 * 32];

        // B hi: quad-major, each __ldg coalesced (lane stride 16B)
        const uint4* bHi = BfQ + (((0 * KS16 + ks) * 4 + ng) * 4) * 32 + lane;
        uint4 bh0 = __ldg(bHi + 0 * 32);
        uint4 bh1 = __ldg(bHi + 1 * 32);
        uint4 bh2 = __ldg(bHi + 2 * 32);
        uint4 bh3 = __ldg(bHi + 3 * 32);

        // pass hh + lh (share Bhi)
        mma16(acc[0][0], a0h, bh0.x, bh0.y);  mma16(acc[0][1], a0h, bh0.z, bh0.w);
        mma16(acc[0][2], a0h, bh1.x, bh1.y);  mma16(acc[0][3], a0h, bh1.z, bh1.w);
        mma16(acc[0][4], a0h, bh2.x, bh2.y);  mma16(acc[0][5], a0h, bh2.z, bh2.w);
        mma16(acc[0][6], a0h, bh3.x, bh3.y);  mma16(acc[0][7], a0h, bh3.z, bh3.w);
        mma16(acc[1][0], a1h, bh0.x, bh0.y);  mma16(acc[1][1], a1h, bh0.z, bh0.w);
        mma16(acc[1][2], a1h, bh1.x, bh1.y);  mma16(acc[1][3], a1h, bh1.z, bh1.w);
        mma16(acc[1][4], a1h, bh2.x, bh2.y);  mma16(acc[1][5], a1h, bh2.z, bh2.w);
        mma16(acc[1][6], a1h, bh3.x, bh3.y);  mma16(acc[1][7], a1h, bh3.z, bh3.w);

        mma16(acc[0][0], a0l, bh0.x, bh0.y);  mma16(acc[0][1], a0l, bh0.z, bh0.w);
        mma16(acc[0][2], a0l, bh1.x, bh1.y);  mma16(acc[0][3], a0l, bh1.z, bh1.w);
        mma16(acc[0][4], a0l, bh2.x, bh2.y);  mma16(acc[0][5], a0l, bh2.z, bh2.w);
        mma16(acc[0][6], a0l, bh3.x, bh3.y);  mma16(acc[0][7], a0l, bh3.z, bh3.w);
        mma16(acc[1][0], a1l, bh0.x, bh0.y);  mma16(acc[1][1], a1l, bh0.z, bh0.w);
        mma16(acc[1][2], a1l, bh1.x, bh1.y);  mma16(acc[1][3], a1l, bh1.z, bh1.w);
        mma16(acc[1][4], a1l, bh2.x, bh2.y);  mma16(acc[1][5], a1l, bh2.z, bh2.w);
        mma16(acc[1][6], a1l, bh3.x, bh3.y);  mma16(acc[1][7], a1l, bh3.z, bh3.w);

        // B lo: quad-major, coalesced
        const uint4* bLo = BfQ + (((1 * KS16 + ks) * 4 + ng) * 4) * 32 + lane;
        uint4 bl0 = __ldg(bLo + 0 * 32);
        uint4 bl1 = __ldg(bLo + 1 * 32);
        uint4 bl2 = __ldg(bLo + 2 * 32);
        uint4 bl3 = __ldg(bLo + 3 * 32);

        // pass hl
        mma16(acc[0][0], a0h, bl0.x, bl0.y);  mma16(acc[0][1], a0h, bl0.z, bl0.w);
        mma16(acc[0][2], a0h, bl1.x, bl1.y);  mma16(acc[0][3], a0h, bl1.z, bl1.w);
        mma16(acc[0][4], a0h, bl2.x, bl2.y);  mma16(acc[0][5], a0h, bl2.z, bl2.w);
        mma16(acc[0][6], a0h, bl3.x, bl3.y);  mma16(acc[0][7], a0h, bl3.z, bl3.w);
        mma16(acc[1][0], a1h, bl0.x, bl0.y);  mma16(acc[1][1], a1h, bl0.z, bl0.w);
        mma16(acc[1][2], a1h, bl1.x, bl1.y);  mma16(acc[1][3], a1h, bl1.z, bl1.w);
        mma16(acc[1][4], a1h, bl2.x, bl2.y);  mma16(acc[1][5], a1h, bl2.z, bl2.w);
        mma16(acc[1][6], a1h, bl3.x, bl3.y);  mma16(acc[1][7], a1h, bl3.z, bl3.w);
    }

    // ---- epilogue: acc -> hr / ho ----
    float* dst = (ng < 2) ? hr : ho;
    const int colbase = (ng & 1) * 64;
    #pragma unroll
    for (int mt = 0; mt < 2; mt++) {
        int row = n0 + mg * 32 + mt * 16 + (lane >> 2);
        #pragma unroll
        for (int nt = 0; nt < 8; nt++) {
            int col = colbase + nt * 8 + 2 * (lane & 3);
            if (row < N_NODES)
                *reinterpret_cast<float2*>(dst + (size_t)row * 128 + col) =
                    make_float2(acc[mt][nt][0], acc[mt][nt][1]);
            if (row + 8 < N_NODES)
                *reinterpret_cast<float2*>(dst + (size_t)(row + 8) * 128 + col) =
                    make_float2(acc[mt][nt][2], acc[mt][nt][3]);
        }
    }
}

#define GEMM_SMEM(K) (64 * ((K) + 4) * 4 + (K) * 256)

// === fused gather + root + BN + ReLU:  out = relu((Σ ew*hr[src] + ho)*s + t)
__global__ void gather_fused_kernel(const float* __restrict__ hr,
                                    const float* __restrict__ ho,
                                    const int* __restrict__ rowptr,
                                    const int* __restrict__ csr_src,
                                    const float* __restrict__ csr_ew,
                                    const float* __restrict__ scale,
                                    const float* __restrict__ shift,
                                    float* __restrict__ out)
{
    int node = (blockIdx.x * blockDim.x + threadIdx.x) >> 5;
    if (node >= N_NODES) return;
    int lane = threadIdx.x & 31;
    int beg = __ldg(rowptr + node);
    int end = __ldg(rowptr + node + 1);

    const float4* hr4 = reinterpret_cast<const float4*>(hr);
    float4 acc = *(reinterpret_cast<const float4*>(ho + (size_t)node * 128) + lane);

    int i = beg;
    for (; i + 3 < end; i += 4) {
        int   s0 = __ldg(csr_src + i);
        int   s1 = __ldg(csr_src + i + 1);
        int   s2 = __ldg(csr_src + i + 2);
        int   s3 = __ldg(csr_src + i + 3);
        float e0 = __ldg(csr_ew + i);
        float e1 = __ldg(csr_ew + i + 1);
        float e2 = __ldg(csr_ew + i + 2);
        float e3 = __ldg(csr_ew + i + 3);
        float4 v0 = hr4[(size_t)s0 * 32 + lane];
        float4 v1 = hr4[(size_t)s1 * 32 + lane];
        float4 v2 = hr4[(size_t)s2 * 32 + lane];
        float4 v3 = hr4[(size_t)s3 * 32 + lane];
        acc.x = fmaf(v0.x, e0, acc.x); acc.y = fmaf(v0.y, e0, acc.y);
        acc.z = fmaf(v0.z, e0, acc.z); acc.w = fmaf(v0.w, e0, acc.w);
        acc.x = fmaf(v1.x, e1, acc.x); acc.y = fmaf(v1.y, e1, acc.y);
        acc.z = fmaf(v1.z, e1, acc.z); acc.w = fmaf(v1.w, e1, acc.w);
        acc.x = fmaf(v2.x, e2, acc.x); acc.y = fmaf(v2.y, e2, acc.y);
        acc.z = fmaf(v2.z, e2, acc.z); acc.w = fmaf(v2.w, e2, acc.w);
        acc.x = fmaf(v3.x, e3, acc.x); acc.y = fmaf(v3.y, e3, acc.y);
        acc.z = fmaf(v3.z, e3, acc.z); acc.w = fmaf(v3.w, e3, acc.w);
    }
    for (; i < end; i++) {
        int   s0 = __ldg(csr_src + i);
        float e0 = __ldg(csr_ew + i);
        float4 v0 = hr4[(size_t)s0 * 32 + lane];
        acc.x = fmaf(v0.x, e0, acc.x); acc.y = fmaf(v0.y, e0, acc.y);
        acc.z = fmaf(v0.z, e0, acc.z); acc.w = fmaf(v0.w, e0, acc.w);
    }

    float4 sc = *(reinterpret_cast<const float4*>(scale) + lane);
    float4 sh = *(reinterpret_cast<const float4*>(shift) + lane);
    float4 res;
    res.x = fmaxf(fmaf(acc.x, sc.x, sh.x), 0.f);
    res.y = fmaxf(fmaf(acc.y, sc.y, sh.y), 0.f);
    res.z = fmaxf(fmaf(acc.z, sc.z, sh.z), 0.f);
    res.w = fmaxf(fmaf(acc.w, sc.w, sh.w), 0.f);
    *(reinterpret_cast<float4*>(out + (size_t)node * 128) + lane) = res;
}

// ------------- fused mean-pool + head (block per graph) ------------------
__global__ void pool_head_kernel(const float* __restrict__ h,
                                 const int* __restrict__ batch,
                                 const float* __restrict__ W1,
                                 const float* __restrict__ b1,
                                 const float* __restrict__ W2,
                                 const float* __restrict__ b2,
                                 float* __restrict__ out)
{
    __shared__ float sp[HIDDEN];
    __shared__ float sred[128];
    __shared__ int srange[2];
    const int g = blockIdx.x;
    const int t = threadIdx.x;

    if (t < 2) {
        int key = g + t;
        int lo = 0, hi = N_NODES;
        while (lo < hi) {
            int mid = (lo + hi) >> 1;
            if (__ldg(batch + mid) < key) lo = mid + 1; else hi = mid;
        }
        srange[t] = lo;
    }
    __syncthreads();
    const int start = srange[0];
    const int end   = srange[1];

    float sum = 0.f;
    for (int n = start; n < end; n++)
        sum += h[(size_t)n * HIDDEN + t];
    float inv = 1.0f / fmaxf((float)(end - start), 1.0f);
    sp[t] = sum * inv;
    __syncthreads();

    float val = 0.f;
    if (t < 64) {
        float acc = __ldg(b1 + t);
        #pragma unroll 8
        for (int k = 0; k < HIDDEN; k++)
            acc = fmaf(sp[k], __ldg(W1 + k * 64 + t), acc);
        val = fmaxf(acc, 0.f) * __ldg(W2 + t);
    }
    sred[t] = val;
    __syncthreads();
    for (int s = 64; s > 0; s >>= 1) {
        if (t < s) sred[t] += sred[t + s];
        __syncthreads();
    }
    if (t == 0) out[g] = sred[0] + __ldg(b2);
}

// -------------------------------------------------------------------------
extern "C" void kernel_launch(void* const* d_in, const int* in_sizes, int n_in,
                              void* d_out, int out_size)
{
    (void)in_sizes; (void)n_in; (void)out_size;
    const float* x     = (const float*)d_in[0];
    const int*   ei    = (const int*)  d_in[1];
    const float* ea    = (const float*)d_in[2];
    const int*   batch = (const int*)  d_in[3];
    const float* P[21];
    for (int i = 0; i < 21; i++) P[i] = (const float*)d_in[4 + i];
    const float* head_w1 = (const float*)d_in[25];
    const float* head_b1 = (const float*)d_in[26];
    const float* head_w2 = (const float*)d_in[27];
    const float* head_b2 = (const float*)d_in[28];
    float* out = (float*)d_out;

    float *hr, *ho, *ha, *hb, *scale, *shift;
    uint32_t* Bf;
    int *deg, *incl, *bsum, *boff, *rowptr, *cursor, *csr_src;
    float *csr_ew;
    cudaGetSymbolAddress((void**)&hr,      g_hr);
    cudaGetSymbolAddress((void**)&ho,      g_ho);
    cudaGetSymbolAddress((void**)&ha,      g_ha);
    cudaGetSymbolAddress((void**)&hb,      g_hb);
    cudaGetSymbolAddress((void**)&scale,   g_scale);
    cudaGetSymbolAddress((void**)&shift,   g_shift);
    cudaGetSymbolAddress((void**)&Bf,      g_Bf);
    cudaGetSymbolAddress((void**)&deg,     g_deg);
    cudaGetSymbolAddress((void**)&incl,    g_incl);
    cudaGetSymbolAddress((void**)&bsum,    g_bsum);
    cudaGetSymbolAddress((void**)&boff,    g_boff);
    cudaGetSymbolAddress((void**)&rowptr,  g_rowptr);
    cudaGetSymbolAddress((void**)&cursor,  g_cursor);
    cudaGetSymbolAddress((void**)&csr_src, g_csr_src);
    cudaGetSymbolAddress((void**)&csr_ew,  g_csr_ew);

    cudaFuncSetAttribute(gemm_mma_kernel<4>,
                         cudaFuncAttributeMaxDynamicSharedMemorySize, GEMM_SMEM(64));
    cudaFuncSetAttribute(gemm_mma_kernel<8>,
                         cudaFuncAttributeMaxDynamicSharedMemorySize, GEMM_SMEM(128));

    const int* src = ei;
    const int* dst = ei + N_EDGES;

    const int gather_blocks = (N_NODES * 32 + 255) / 256;

    // Launch order: 6th launch (ncu -s 5 -c 1) is gemm layer 0.
    prep_weights_kernel<<<(16384 + 32768 + 32768 + 255) / 256, 256>>>(
        P[0], P[2], P[7], P[9], P[14], P[16]);                       // 1
    cudaMemsetAsync(deg,    0, N_NODES * sizeof(int), 0);            // 2
    cudaMemsetAsync(cursor, 0, N_NODES * sizeof(int), 0);            // 3
    hist_kernel<<<(N_EDGES + 255) / 256, 256>>>(dst, deg);           // 4
    scan1_kernel<<<N_SCAN_BLOCKS, SCAN_BLK>>>(deg, incl, bsum);      // 5
    gemm_mma_kernel<4><<<N_TILES64, 256, GEMM_SMEM(64)>>>(x, Bf, hr, ho); // 6 (profiled)
    scan2_kernel<<<1, 512>>>(bsum, boff);                            // 7
    scan3_kernel<<<(N_NODES + 255) / 256, 256>>>(deg, incl, boff, rowptr); // 8
    fill_kernel<<<(N_EDGES + 255) / 256, 256>>>(src, dst, ea, rowptr, cursor,
                                                csr_src, csr_ew);    // 9
    bn_fold_kernel<<<3, 128>>>(P[1], P[3], P[4], P[5], P[6],
                               P[8], P[10], P[11], P[12], P[13],
                               P[15], P[17], P[18], P[19], P[20]);   // 10

    // ---- Layer 0 gather ----
    gather_fused_kernel<<<gather_blocks, 256>>>(hr, ho, rowptr, csr_src, csr_ew,
                                                scale + 0 * HIDDEN, shift + 0 * HIDDEN, ha);

    // ---- Layer 1 ----
    gemm_mma_kernel<8><<<N_TILES64, 256, GEMM_SMEM(128)>>>(ha, Bf + 16384, hr, ho);
    gather_fused_kernel<<<gather_blocks, 256>>>(hr, ho, rowptr, csr_src, csr_ew,
                                                scale + 1 * HIDDEN, shift + 1 * HIDDEN, hb);

    // ---- Layer 2 ----
    gemm_mma_kernel<8><<<N_TILES64, 256, GEMM_SMEM(128)>>>(hb, Bf + 49152, hr, ho);
    gather_fused_kernel<<<gather_blocks, 256>>>(hr, ho, rowptr, csr_src, csr_ew,
                                                scale + 2 * HIDDEN, shift + 2 * HIDDEN, ha);

    // ---- Fused mean pool + head ----
    pool_head_kernel<<<N_GRAPHS, 128>>>(ha, batch, head_w1, head_b1,
                                        head_w2, head_b2, out);
}

// round 11
// speedup vs baseline: 1.7814x; 1.0733x over previous
#include <cuda_runtime.h>
#include <cstdint>
#include <cstddef>

#define N_NODES 100000
#define N_EDGES 1600000
#define F_IN    64
#define HIDDEN  128
#define N_GRAPHS 1024
#define EPS 1e-5f

#define SCAN_BLK 256
#define N_SCAN_BLOCKS ((N_NODES + SCAN_BLK - 1) / SCAN_BLK)   // 391
#define N_TILES64 ((N_NODES + 63) / 64)                        // 1563

// ---------------- static scratch (no allocation allowed) ----------------
__device__ float g_hr[(size_t)N_NODES * HIDDEN];    // hr (layers 1,2)
__device__ float g_ho[(size_t)N_NODES * HIDDEN];    // ho (layers 1,2) / agg0
__device__ float g_ha[(size_t)N_NODES * HIDDEN];
__device__ float g_hb[(size_t)N_NODES * HIDDEN];

__device__ float g_scale[3][HIDDEN];
__device__ float g_shift[3][HIDDEN];

// bf16-split B fragments, QUAD-MAJOR coalesced (packed bf16x2 words).
// layer0 (fused, N=128, K'=128): 16384 words at offset 0
//   word = ((((hilo*8+ks)*2+ng)*4+q)*32+lane)*4+w
// layers1/2 (N=256, K=128): 32768 words at 16384 / 49152
//   word = ((((hilo*8+ks)*4+ng)*4+q)*32+lane)*4+w
__device__ __align__(16) uint32_t g_Bf[16384 + 32768 + 32768];

__device__ int   g_dc[2 * N_NODES];                 // [deg | cursor]
__device__ int   g_incl[N_SCAN_BLOCKS * SCAN_BLK];
__device__ int   g_bsum[N_SCAN_BLOCKS];
__device__ int   g_boff[N_SCAN_BLOCKS];
__device__ int   g_csr_src[N_EDGES];
__device__ float g_csr_ew[N_EDGES];

__device__ __forceinline__ uint32_t bf16x2(float x0, float x1) {
    uint32_t r;
    asm("cvt.rn.bf16x2.f32 %0, %1, %2;" : "=r"(r) : "f"(x1), "f"(x0));
    return r;
}

__device__ __forceinline__ void mma16(float* c, uint4 a, uint32_t b0, uint32_t b1) {
    asm volatile(
        "mma.sync.aligned.m16n8k16.row.col.f32.bf16.bf16.f32 "
        "{%0,%1,%2,%3}, {%4,%5,%6,%7}, {%8,%9}, {%0,%1,%2,%3};"
        : "+f"(c[0]), "+f"(c[1]), "+f"(c[2]), "+f"(c[3])
        : "r"(a.x), "r"(a.y), "r"(a.z), "r"(a.w), "r"(b0), "r"(b1));
}

// ======================= CSR build (by dst, no rowptr array) =============
__global__ void hist_kernel(const int* __restrict__ dst, int* __restrict__ deg)
{
    int e = blockIdx.x * blockDim.x + threadIdx.x;
    if (e < N_EDGES) atomicAdd(deg + __ldg(dst + e), 1);
}

__global__ void scan1_kernel(const int* __restrict__ deg,
                             int* __restrict__ incl, int* __restrict__ bsum)
{
    __shared__ int s[SCAN_BLK];
    int gid = blockIdx.x * SCAN_BLK + threadIdx.x;
    int v = (gid < N_NODES) ? deg[gid] : 0;
    s[threadIdx.x] = v;
    __syncthreads();
    #pragma unroll
    for (int off = 1; off < SCAN_BLK; off <<= 1) {
        int t = (threadIdx.x >= off) ? s[threadIdx.x - off] : 0;
        __syncthreads();
        s[threadIdx.x] += t;
        __syncthreads();
    }
    incl[gid] = s[threadIdx.x];
    if (threadIdx.x == SCAN_BLK - 1) bsum[blockIdx.x] = s[threadIdx.x];
}

__global__ void scan2_kernel(const int* __restrict__ bsum, int* __restrict__ boff)
{
    __shared__ int s[512];
    int t = threadIdx.x;
    s[t] = (t < N_SCAN_BLOCKS) ? bsum[t] : 0;
    __syncthreads();
    #pragma unroll
    for (int off = 1; off < 512; off <<= 1) {
        int v = (t >= off) ? s[t - off] : 0;
        __syncthreads();
        s[t] += v;
        __syncthreads();
    }
    if (t < N_SCAN_BLOCKS) boff[t] = s[t] - bsum[t];   // exclusive
}

// fill with inline rowptr: base = incl[d] - deg[d] + boff[d>>8]
__global__ void fill_kernel(const int* __restrict__ src,
                            const int* __restrict__ dst,
                            const float* __restrict__ ew,
                            const int* __restrict__ deg,
                            const int* __restrict__ incl,
                            const int* __restrict__ boff,
                            int* __restrict__ cursor,
                            int* __restrict__ csr_src,
                            float* __restrict__ csr_ew)
{
    int e = blockIdx.x * blockDim.x + threadIdx.x;
    if (e >= N_EDGES) return;
    int d = __ldg(dst + e);
    int base = __ldg(incl + d) - __ldg(deg + d) + __ldg(boff + (d >> 8));
    int pos = atomicAdd(cursor + d, 1);
    int idx = base + pos;
    csr_src[idx] = __ldg(src + e);
    csr_ew[idx]  = __ldg(ew + e);
}

// ---------------- fold BN params (+rel bias) into scale/shift -------------
__global__ void bn_fold_kernel(const float* __restrict__ br0, const float* __restrict__ g0,
                               const float* __restrict__ b0,  const float* __restrict__ m0,
                               const float* __restrict__ v0,
                               const float* __restrict__ br1, const float* __restrict__ g1,
                               const float* __restrict__ b1,  const float* __restrict__ m1,
                               const float* __restrict__ v1,
                               const float* __restrict__ br2, const float* __restrict__ g2,
                               const float* __restrict__ b2,  const float* __restrict__ m2,
                               const float* __restrict__ v2)
{
    int j = threadIdx.x;
    int l = blockIdx.x;
    const float* br = (l == 0) ? br0 : (l == 1) ? br1 : br2;
    const float* g  = (l == 0) ? g0  : (l == 1) ? g1  : g2;
    const float* b  = (l == 0) ? b0  : (l == 1) ? b1  : b2;
    const float* m  = (l == 0) ? m0  : (l == 1) ? m1  : m2;
    const float* v  = (l == 0) ? v0  : (l == 1) ? v1  : v2;
    float s = g[j] * rsqrtf(v[j] + EPS);
    g_scale[l][j] = s;
    g_shift[l][j] = (br[j] - m[j]) * s + b[j];
}

// ---- prep layer0 (fused-GEMM image): virtual K'=128 = [Wr0(64);Wo0(64)], N=128
__global__ void prep0_kernel(const float* __restrict__ Wr0, const float* __restrict__ Wo0)
{
    int rem = blockIdx.x * blockDim.x + threadIdx.x;
    if (rem >= 16384) return;
    int w    = rem & 3;
    int lane = (rem >> 2) & 31;
    int q    = (rem >> 7) & 3;
    int ng   = (rem >> 9) & 1;
    int t    = rem >> 10;            // 0..15
    int ks   = t & 7;
    int hilo = t >> 3;
    int idx  = q * 4 + w;
    int nt = idx >> 1, breg = idx & 1;
    int k0 = ks * 16 + (lane & 3) * 2 + breg * 8;     // virtual k, even
    int n  = ng * 64 + nt * 8 + (lane >> 2);          // 0..127
    float w0, w1;
    if (k0 < 64) { w0 = __ldg(Wr0 + k0 * 128 + n); w1 = __ldg(Wr0 + (k0 + 1) * 128 + n); }
    else         { w0 = __ldg(Wo0 + (k0 - 64) * 128 + n); w1 = __ldg(Wo0 + (k0 - 63) * 128 + n); }
    uint32_t hw = bf16x2(w0, w1);
    uint32_t out = hw;
    if (hilo) {
        float h0 = __uint_as_float(hw << 16);
        float h1 = __uint_as_float(hw & 0xffff0000u);
        out = bf16x2(w0 - h0, w1 - h1);
    }
    g_Bf[rem] = out;
}

// ---- prep layers 1/2 (GEMM-first image): N=256 = [Wr|Wo], K=128 ----------
__global__ void prep12_kernel(const float* __restrict__ Wr1, const float* __restrict__ Wo1,
                              const float* __restrict__ Wr2, const float* __restrict__ Wo2)
{
    int id = blockIdx.x * blockDim.x + threadIdx.x;
    if (id >= 65536) return;
    int base, rem;
    const float *Wr, *Wo;
    if (id < 32768) { base = 16384; rem = id;          Wr = Wr1; Wo = Wo1; }
    else            { base = 49152; rem = id - 32768;  Wr = Wr2; Wo = Wo2; }
    int w    = rem & 3;
    int lane = (rem >> 2) & 31;
    int q    = (rem >> 7) & 3;
    int ng   = (rem >> 9) & 3;
    int t    = rem >> 11;            // 0..15
    int ks   = t & 7;
    int hilo = t >> 3;
    int idx  = q * 4 + w;
    int nt = idx >> 1, breg = idx & 1;
    int k0 = ks * 16 + (lane & 3) * 2 + breg * 8;
    int n  = ng * 64 + nt * 8 + (lane >> 2);
    int jj = n & 127;
    const float* W = (n < 128) ? Wr : Wo;
    float w0 = __ldg(W + (k0 + 0) * 128 + jj);
    float w1 = __ldg(W + (k0 + 1) * 128 + jj);
    uint32_t hw = bf16x2(w0, w1);
    uint32_t out = hw;
    if (hilo) {
        float h0 = __uint_as_float(hw << 16);
        float h1 = __uint_as_float(hw & 0xffff0000u);
        out = bf16x2(w0 - h0, w1 - h1);
    }
    g_Bf[base + rem] = out;
}

// ============== plain gather (layer 0): agg[n] = Σ ew*x[src] (D=64) ======
__global__ void gather64_kernel(const float* __restrict__ x,
                                const int* __restrict__ deg,
                                const int* __restrict__ incl,
                                const int* __restrict__ boff,
                                const int* __restrict__ csr_src,
                                const float* __restrict__ csr_ew,
                                float* __restrict__ agg)
{
    int node = (blockIdx.x * blockDim.x + threadIdx.x) >> 5;
    if (node >= N_NODES) return;
    int lane = threadIdx.x & 31;
    int end = __ldg(incl + node) + __ldg(boff + (node >> 8));
    int beg = end - __ldg(deg + node);

    const float2* x2 = reinterpret_cast<const float2*>(x);
    float2 acc = make_float2(0.f, 0.f);
    int i = beg;
    for (; i + 1 < end; i += 2) {
        int   s0 = __ldg(csr_src + i);
        int   s1 = __ldg(csr_src + i + 1);
        float e0 = __ldg(csr_ew + i);
        float e1 = __ldg(csr_ew + i + 1);
        float2 v0 = x2[(size_t)s0 * 32 + lane];
        float2 v1 = x2[(size_t)s1 * 32 + lane];
        acc.x = fmaf(v0.x, e0, acc.x); acc.y = fmaf(v0.y, e0, acc.y);
        acc.x = fmaf(v1.x, e1, acc.x); acc.y = fmaf(v1.y, e1, acc.y);
    }
    if (i < end) {
        int   s0 = __ldg(csr_src + i);
        float e0 = __ldg(csr_ew + i);
        float2 v0 = x2[(size_t)s0 * 32 + lane];
        acc.x = fmaf(v0.x, e0, acc.x); acc.y = fmaf(v0.y, e0, acc.y);
    }
    reinterpret_cast<float2*>(agg + (size_t)node * 64)[lane] = acc;
}

// ====== layer-0 fused GEMM: out = relu(([agg|x] @ [Wr;Wo])*scale+shift) ===
// CTA: 64 rows x 128 cols, 4 warps (mg=w>>1, ng=w&1), warp tile M32xN64.
// K'=128 processed in 2 chunks of 64 (chunk0=agg, chunk1=x). 4 CTAs/SM.
template <int K>   // per-matrix width (64)
__global__ void __launch_bounds__(128, 4)
gemm_fused_kernel(const float* __restrict__ agg, const float* __restrict__ h,
                  const uint32_t* __restrict__ Bf,
                  const float* __restrict__ scale, const float* __restrict__ shift,
                  float* __restrict__ out)
{
    constexpr int KS16T = K / 8;     // total ks16 over K'=2K (8 for K=64)
    constexpr int CHUNKS = K / 32;   // 64-wide chunks (2 for K=64)
    extern __shared__ float smem[];
    float*    sRaw  = smem;                                   // 64*68 floats
    uint32_t* fragU = reinterpret_cast<uint32_t*>(smem + 64 * 68);  // 4096 words

    const int tid  = threadIdx.x;
    const int w    = tid >> 5;       // 0..3
    const int lane = tid & 31;
    const int mg   = w >> 1;         // 0..1
    const int ng   = w & 1;          // 0..1
    const int n0   = blockIdx.x * 64;

    float acc[2][8][4];
    #pragma unroll
    for (int mt = 0; mt < 2; mt++)
        #pragma unroll
        for (int nt = 0; nt < 8; nt++)
            #pragma unroll
            for (int r = 0; r < 4; r++) acc[mt][nt][r] = 0.f;

    const uint4* fragQ = reinterpret_cast<const uint4*>(fragU);
    const uint4* BfQ   = reinterpret_cast<const uint4*>(Bf);

    for (int c = 0; c < CHUNKS; c++) {
        const float* srcP = (c * 64 < K) ? agg : h;
        int coff = (c * 64 < K) ? c * 64 : c * 64 - K;

        // stage raw 64 rows x 64 cols (16 uint4 per row)
        for (int i = tid; i < 1024; i += 128) {
            int row = i >> 4, cc = i & 15;
            uint4 v = make_uint4(0u, 0u, 0u, 0u);
            if (n0 + row < N_NODES)
                v = *reinterpret_cast<const uint4*>(srcP + (size_t)(n0 + row) * K + coff + cc * 4);
            *reinterpret_cast<uint4*>(&sRaw[row * 68 + cc * 4]) = v;
        }
        __syncthreads();

        // convert: warp (mg, par=ng) handles ksl = par + 2j
        #pragma unroll
        for (int j = 0; j < 2; j++) {
            int ksl = (w & 1) + 2 * j;
            int cbase = (mg * 4 + ksl) * 4;
            #pragma unroll
            for (int mt = 0; mt < 2; mt++) {
                uint32_t hwv[4], lwv[4];
                #pragma unroll
                for (int r = 0; r < 4; r++) {
                    int row = mg * 32 + mt * 16 + (lane >> 2) + (r & 1) * 8;
                    int k0  = ksl * 16 + (lane & 3) * 2 + ((r >> 1) & 1) * 8;
                    float x0 = sRaw[row * 68 + k0];
                    float x1 = sRaw[row * 68 + k0 + 1];
                    uint32_t hw = bf16x2(x0, x1);
                    float h0 = __uint_as_float(hw << 16);
                    float h1 = __uint_as_float(hw & 0xffff0000u);
                    hwv[r] = hw;
                    lwv[r] = bf16x2(x0 - h0, x1 - h1);
                }
                *reinterpret_cast<uint4*>(&fragU[((cbase + mt * 2 + 0) * 32 + lane) * 4]) =
                    make_uint4(hwv[0], hwv[1], hwv[2], hwv[3]);
                *reinterpret_cast<uint4*>(&fragU[((cbase + mt * 2 + 1) * 32 + lane) * 4]) =
                    make_uint4(lwv[0], lwv[1], lwv[2], lwv[3]);
            }
        }
        __syncthreads();

        // MMA over local ks 0..3 (global gks = c*4 + ksl)
        for (int ksl = 0; ksl < 4; ksl++) {
            int gks = c * 4 + ksl;
            const uint4* aB = fragQ + ((mg * 4 + ksl) * 4) * 32 + lane;
            uint4 a0h = aB[0 * 32];
            uint4 a0l = aB[1 * 32];
            uint4 a1h = aB[2 * 32];
            uint4 a1l = aB[3 * 32];

            const uint4* bHi = BfQ + (((0 * KS16T + gks) * 2 + ng) * 4) * 32 + lane;
            uint4 bh0 = __ldg(bHi + 0 * 32);
            uint4 bh1 = __ldg(bHi + 1 * 32);
            uint4 bh2 = __ldg(bHi + 2 * 32);
            uint4 bh3 = __ldg(bHi + 3 * 32);

            mma16(acc[0][0], a0h, bh0.x, bh0.y);  mma16(acc[0][1], a0h, bh0.z, bh0.w);
            mma16(acc[0][2], a0h, bh1.x, bh1.y);  mma16(acc[0][3], a0h, bh1.z, bh1.w);
            mma16(acc[0][4], a0h, bh2.x, bh2.y);  mma16(acc[0][5], a0h, bh2.z, bh2.w);
            mma16(acc[0][6], a0h, bh3.x, bh3.y);  mma16(acc[0][7], a0h, bh3.z, bh3.w);
            mma16(acc[1][0], a1h, bh0.x, bh0.y);  mma16(acc[1][1], a1h, bh0.z, bh0.w);
            mma16(acc[1][2], a1h, bh1.x, bh1.y);  mma16(acc[1][3], a1h, bh1.z, bh1.w);
            mma16(acc[1][4], a1h, bh2.x, bh2.y);  mma16(acc[1][5], a1h, bh2.z, bh2.w);
            mma16(acc[1][6], a1h, bh3.x, bh3.y);  mma16(acc[1][7], a1h, bh3.z, bh3.w);

            mma16(acc[0][0], a0l, bh0.x, bh0.y);  mma16(acc[0][1], a0l, bh0.z, bh0.w);
            mma16(acc[0][2], a0l, bh1.x, bh1.y);  mma16(acc[0][3], a0l, bh1.z, bh1.w);
            mma16(acc[0][4], a0l, bh2.x, bh2.y);  mma16(acc[0][5], a0l, bh2.z, bh2.w);
            mma16(acc[0][6], a0l, bh3.x, bh3.y);  mma16(acc[0][7], a0l, bh3.z, bh3.w);
            mma16(acc[1][0], a1l, bh0.x, bh0.y);  mma16(acc[1][1], a1l, bh0.z, bh0.w);
            mma16(acc[1][2], a1l, bh1.x, bh1.y);  mma16(acc[1][3], a1l, bh1.z, bh1.w);
            mma16(acc[1][4], a1l, bh2.x, bh2.y);  mma16(acc[1][5], a1l, bh2.z, bh2.w);
            mma16(acc[1][6], a1l, bh3.x, bh3.y);  mma16(acc[1][7], a1l, bh3.z, bh3.w);

            const uint4* bLo = BfQ + (((1 * KS16T + gks) * 2 + ng) * 4) * 32 + lane;
            uint4 bl0 = __ldg(bLo + 0 * 32);
            uint4 bl1 = __ldg(bLo + 1 * 32);
            uint4 bl2 = __ldg(bLo + 2 * 32);
            uint4 bl3 = __ldg(bLo + 3 * 32);

            mma16(acc[0][0], a0h, bl0.x, bl0.y);  mma16(acc[0][1], a0h, bl0.z, bl0.w);
            mma16(acc[0][2], a0h, bl1.x, bl1.y);  mma16(acc[0][3], a0h, bl1.z, bl1.w);
            mma16(acc[0][4], a0h, bl2.x, bl2.y);  mma16(acc[0][5], a0h, bl2.z, bl2.w);
            mma16(acc[0][6], a0h, bl3.x, bl3.y);  mma16(acc[0][7], a0h, bl3.z, bl3.w);
            mma16(acc[1][0], a1h, bl0.x, bl0.y);  mma16(acc[1][1], a1h, bl0.z, bl0.w);
            mma16(acc[1][2], a1h, bl1.x, bl1.y);  mma16(acc[1][3], a1h, bl1.z, bl1.w);
            mma16(acc[1][4], a1h, bl2.x, bl2.y);  mma16(acc[1][5], a1h, bl2.z, bl2.w);
            mma16(acc[1][6], a1h, bl3.x, bl3.y);  mma16(acc[1][7], a1h, bl3.z, bl3.w);
        }
        __syncthreads();
    }

    // ---- epilogue: BN + bias + ReLU, write 128-col output ----
    #pragma unroll
    for (int mt = 0; mt < 2; mt++) {
        int row = n0 + mg * 32 + mt * 16 + (lane >> 2);
        #pragma unroll
        for (int nt = 0; nt < 8; nt++) {
            int col = ng * 64 + nt * 8 + 2 * (lane & 3);
            float2 sc = *reinterpret_cast<const float2*>(scale + col);
            float2 sh = *reinterpret_cast<const float2*>(shift + col);
            if (row < N_NODES) {
                float2 o;
                o.x = fmaxf(fmaf(acc[mt][nt][0], sc.x, sh.x), 0.f);
                o.y = fmaxf(fmaf(acc[mt][nt][1], sc.y, sh.y), 0.f);
                *reinterpret_cast<float2*>(out + (size_t)row * 128 + col) = o;
            }
            if (row + 8 < N_NODES) {
                float2 o;
                o.x = fmaxf(fmaf(acc[mt][nt][2], sc.x, sh.x), 0.f);
                o.y = fmaxf(fmaf(acc[mt][nt][3], sc.y, sh.y), 0.f);
                *reinterpret_cast<float2*>(out + (size_t)(row + 8) * 128 + col) = o;
            }
        }
    }
}
#define GEMM_FUSED_SMEM (64 * 68 * 4 + 4096 * 4)

// ====== layers 1/2 GEMM (GEMM-first, N=256), as R10 ======================
template <int KS16>
__global__ void __launch_bounds__(256, 2)
gemm_mma_kernel(const float* __restrict__ h,
                const uint32_t* __restrict__ Bf,
                float* __restrict__ hr,
                float* __restrict__ ho)
{
    constexpr int K = KS16 * 16;
    extern __shared__ float smem[];
    float*    sRaw  = smem;
    uint32_t* fragU = reinterpret_cast<uint32_t*>(smem + 64 * (K + 4));

    const int tid  = threadIdx.x;
    const int w    = tid >> 5;
    const int lane = tid & 31;
    const int mg   = w >> 2;
    const int ng   = w & 3;
    const int n0   = blockIdx.x * 64;

    for (int i = tid; i < 16 * K; i += 256) {
        int row = i / (K / 4);
        int c   = i % (K / 4);
        uint4 v = make_uint4(0u, 0u, 0u, 0u);
        if (n0 + row < N_NODES)
            v = *reinterpret_cast<const uint4*>(h + (size_t)(n0 + row) * K + c * 4);
        *reinterpret_cast<uint4*>(&sRaw[row * (K + 4) + c * 4]) = v;
    }
    __syncthreads();

    for (int j = 0; j < KS16 / 4; j++) {
        int ks = ng + 4 * j;
        int cbase = (mg * KS16 + ks) * 4;
        #pragma unroll
        for (int mt = 0; mt < 2; mt++) {
            uint32_t hwv[4], lwv[4];
            #pragma unroll
            for (int r = 0; r < 4; r++) {
                int row = mg * 32 + mt * 16 + (lane >> 2) + (r & 1) * 8;
                int k0  = ks * 16 + (lane & 3) * 2 + ((r >> 1) & 1) * 8;
                float x0 = sRaw[row * (K + 4) + k0];
                float x1 = sRaw[row * (K + 4) + k0 + 1];
                uint32_t hw = bf16x2(x0, x1);
                float h0 = __uint_as_float(hw << 16);
                float h1 = __uint_as_float(hw & 0xffff0000u);
                hwv[r] = hw;
                lwv[r] = bf16x2(x0 - h0, x1 - h1);
            }
            *reinterpret_cast<uint4*>(&fragU[((cbase + mt * 2 + 0) * 32 + lane) * 4]) =
                make_uint4(hwv[0], hwv[1], hwv[2], hwv[3]);
            *reinterpret_cast<uint4*>(&fragU[((cbase + mt * 2 + 1) * 32 + lane) * 4]) =
                make_uint4(lwv[0], lwv[1], lwv[2], lwv[3]);
        }
    }
    __syncthreads();

    float acc[2][8][4];
    #pragma unroll
    for (int mt = 0; mt < 2; mt++)
        #pragma unroll
        for (int nt = 0; nt < 8; nt++)
            #pragma unroll
            for (int r = 0; r < 4; r++) acc[mt][nt][r] = 0.f;

    const uint4* fragQ = reinterpret_cast<const uint4*>(fragU);
    const uint4* BfQ   = reinterpret_cast<const uint4*>(Bf);

    for (int ks = 0; ks < KS16; ks++) {
        const uint4* aB = fragQ + ((mg * KS16 + ks) * 4) * 32 + lane;
        uint4 a0h = aB[0 * 32];
        uint4 a0l = aB[1 * 32];
        uint4 a1h = aB[2 * 32];
        uint4 a1l = aB[3 * 32];

        const uint4* bHi = BfQ + (((0 * KS16 + ks) * 4 + ng) * 4) * 32 + lane;
        uint4 bh0 = __ldg(bHi + 0 * 32);
        uint4 bh1 = __ldg(bHi + 1 * 32);
        uint4 bh2 = __ldg(bHi + 2 * 32);
        uint4 bh3 = __ldg(bHi + 3 * 32);

        mma16(acc[0][0], a0h, bh0.x, bh0.y);  mma16(acc[0][1], a0h, bh0.z, bh0.w);
        mma16(acc[0][2], a0h, bh1.x, bh1.y);  mma16(acc[0][3], a0h, bh1.z, bh1.w);
        mma16(acc[0][4], a0h, bh2.x, bh2.y);  mma16(acc[0][5], a0h, bh2.z, bh2.w);
        mma16(acc[0][6], a0h, bh3.x, bh3.y);  mma16(acc[0][7], a0h, bh3.z, bh3.w);
        mma16(acc[1][0], a1h, bh0.x, bh0.y);  mma16(acc[1][1], a1h, bh0.z, bh0.w);
        mma16(acc[1][2], a1h, bh1.x, bh1.y);  mma16(acc[1][3], a1h, bh1.z, bh1.w);
        mma16(acc[1][4], a1h, bh2.x, bh2.y);  mma16(acc[1][5], a1h, bh2.z, bh2.w);
        mma16(acc[1][6], a1h, bh3.x, bh3.y);  mma16(acc[1][7], a1h, bh3.z, bh3.w);

        mma16(acc[0][0], a0l, bh0.x, bh0.y);  mma16(acc[0][1], a0l, bh0.z, bh0.w);
        mma16(acc[0][2], a0l, bh1.x, bh1.y);  mma16(acc[0][3], a0l, bh1.z, bh1.w);
        mma16(acc[0][4], a0l, bh2.x, bh2.y);  mma16(acc[0][5], a0l, bh2.z, bh2.w);
        mma16(acc[0][6], a0l, bh3.x, bh3.y);  mma16(acc[0][7], a0l, bh3.z, bh3.w);
        mma16(acc[1][0], a1l, bh0.x, bh0.y);  mma16(acc[1][1], a1l, bh0.z, bh0.w);
        mma16(acc[1][2], a1l, bh1.x, bh1.y);  mma16(acc[1][3], a1l, bh1.z, bh1.w);
        mma16(acc[1][4], a1l, bh2.x, bh2.y);  mma16(acc[1][5], a1l, bh2.z, bh2.w);
        mma16(acc[1][6], a1l, bh3.x, bh3.y);  mma16(acc[1][7], a1l, bh3.z, bh3.w);

        const uint4* bLo = BfQ + (((1 * KS16 + ks) * 4 + ng) * 4) * 32 + lane;
        uint4 bl0 = __ldg(bLo + 0 * 32);
        uint4 bl1 = __ldg(bLo + 1 * 32);
        uint4 bl2 = __ldg(bLo + 2 * 32);
        uint4 bl3 = __ldg(bLo + 3 * 32);

        mma16(acc[0][0], a0h, bl0.x, bl0.y);  mma16(acc[0][1], a0h, bl0.z, bl0.w);
        mma16(acc[0][2], a0h, bl1.x, bl1.y);  mma16(acc[0][3], a0h, bl1.z, bl1.w);
        mma16(acc[0][4], a0h, bl2.x, bl2.y);  mma16(acc[0][5], a0h, bl2.z, bl2.w);
        mma16(acc[0][6], a0h, bl3.x, bl3.y);  mma16(acc[0][7], a0h, bl3.z, bl3.w);
        mma16(acc[1][0], a1h, bl0.x, bl0.y);  mma16(acc[1][1], a1h, bl0.z, bl0.w);
        mma16(acc[1][2], a1h, bl1.x, bl1.y);  mma16(acc[1][3], a1h, bl1.z, bl1.w);
        mma16(acc[1][4], a1h, bl2.x, bl2.y);  mma16(acc[1][5], a1h, bl2.z, bl2.w);
        mma16(acc[1][6], a1h, bl3.x, bl3.y);  mma16(acc[1][7], a1h, bl3.z, bl3.w);
    }

    float* dst = (ng < 2) ? hr : ho;
    const int colbase = (ng & 1) * 64;
    #pragma unroll
    for (int mt = 0; mt < 2; mt++) {
        int row = n0 + mg * 32 + mt * 16 + (lane >> 2);
        #pragma unroll
        for (int nt = 0; nt < 8; nt++) {
            int col = colbase + nt * 8 + 2 * (lane & 3);
            if (row < N_NODES)
                *reinterpret_cast<float2*>(dst + (size_t)row * 128 + col) =
                    make_float2(acc[mt][nt][0], acc[mt][nt][1]);
            if (row + 8 < N_NODES)
                *reinterpret_cast<float2*>(dst + (size_t)(row + 8) * 128 + col) =
                    make_float2(acc[mt][nt][2], acc[mt][nt][3]);
        }
    }
}
#define GEMM_SMEM(K) (64 * ((K) + 4) * 4 + (K) * 256)

// === fused gather + root + BN + ReLU (layers 1/2) =========================
__global__ void gather_fused_kernel(const float* __restrict__ hr,
                                    const float* __restrict__ ho,
                                    const int* __restrict__ deg,
                                    const int* __restrict__ incl,
                                    const int* __restrict__ boff,
                                    const int* __restrict__ csr_src,
                                    const float* __restrict__ csr_ew,
                                    const float* __restrict__ scale,
                                    const float* __restrict__ shift,
                                    float* __restrict__ out)
{
    int node = (blockIdx.x * blockDim.x + threadIdx.x) >> 5;
    if (node >= N_NODES) return;
    int lane = threadIdx.x & 31;
    int end = __ldg(incl + node) + __ldg(boff + (node >> 8));
    int beg = end - __ldg(deg + node);

    const float4* hr4 = reinterpret_cast<const float4*>(hr);
    float4 acc = *(reinterpret_cast<const float4*>(ho + (size_t)node * 128) + lane);

    int i = beg;
    for (; i + 3 < end; i += 4) {
        int   s0 = __ldg(csr_src + i);
        int   s1 = __ldg(csr_src + i + 1);
        int   s2 = __ldg(csr_src + i + 2);
        int   s3 = __ldg(csr_src + i + 3);
        float e0 = __ldg(csr_ew + i);
        float e1 = __ldg(csr_ew + i + 1);
        float e2 = __ldg(csr_ew + i + 2);
        float e3 = __ldg(csr_ew + i + 3);
        float4 v0 = hr4[(size_t)s0 * 32 + lane];
        float4 v1 = hr4[(size_t)s1 * 32 + lane];
        float4 v2 = hr4[(size_t)s2 * 32 + lane];
        float4 v3 = hr4[(size_t)s3 * 32 + lane];
        acc.x = fmaf(v0.x, e0, acc.x); acc.y = fmaf(v0.y, e0, acc.y);
        acc.z = fmaf(v0.z, e0, acc.z); acc.w = fmaf(v0.w, e0, acc.w);
        acc.x = fmaf(v1.x, e1, acc.x); acc.y = fmaf(v1.y, e1, acc.y);
        acc.z = fmaf(v1.z, e1, acc.z); acc.w = fmaf(v1.w, e1, acc.w);
        acc.x = fmaf(v2.x, e2, acc.x); acc.y = fmaf(v2.y, e2, acc.y);
        acc.z = fmaf(v2.z, e2, acc.z); acc.w = fmaf(v2.w, e2, acc.w);
        acc.x = fmaf(v3.x, e3, acc.x); acc.y = fmaf(v3.y, e3, acc.y);
        acc.z = fmaf(v3.z, e3, acc.z); acc.w = fmaf(v3.w, e3, acc.w);
    }
    for (; i < end; i++) {
        int   s0 = __ldg(csr_src + i);
        float e0 = __ldg(csr_ew + i);
        float4 v0 = hr4[(size_t)s0 * 32 + lane];
        acc.x = fmaf(v0.x, e0, acc.x); acc.y = fmaf(v0.y, e0, acc.y);
        acc.z = fmaf(v0.z, e0, acc.z); acc.w = fmaf(v0.w, e0, acc.w);
    }

    float4 sc = *(reinterpret_cast<const float4*>(scale) + lane);
    float4 sh = *(reinterpret_cast<const float4*>(shift) + lane);
    float4 res;
    res.x = fmaxf(fmaf(acc.x, sc.x, sh.x), 0.f);
    res.y = fmaxf(fmaf(acc.y, sc.y, sh.y), 0.f);
    res.z = fmaxf(fmaf(acc.z, sc.z, sh.z), 0.f);
    res.w = fmaxf(fmaf(acc.w, sc.w, sh.w), 0.f);
    *(reinterpret_cast<float4*>(out + (size_t)node * 128) + lane) = res;
}

// ------------- fused mean-pool + head (block per graph) ------------------
__global__ void pool_head_kernel(const float* __restrict__ h,
                                 const int* __restrict__ batch,
                                 const float* __restrict__ W1,
                                 const float* __restrict__ b1,
                                 const float* __restrict__ W2,
                                 const float* __restrict__ b2,
                                 float* __restrict__ out)
{
    __shared__ float sp[HIDDEN];
    __shared__ float sred[128];
    __shared__ int srange[2];
    const int g = blockIdx.x;
    const int t = threadIdx.x;

    if (t < 2) {
        int key = g + t;
        int lo = 0, hi = N_NODES;
        while (lo < hi) {
            int mid = (lo + hi) >> 1;
            if (__ldg(batch + mid) < key) lo = mid + 1; else hi = mid;
        }
        srange[t] = lo;
    }
    __syncthreads();
    const int start = srange[0];
    const int end   = srange[1];

    float sum = 0.f;
    for (int n = start; n < end; n++)
        sum += h[(size_t)n * HIDDEN + t];
    float inv = 1.0f / fmaxf((float)(end - start), 1.0f);
    sp[t] = sum * inv;
    __syncthreads();

    float val = 0.f;
    if (t < 64) {
        float acc = __ldg(b1 + t);
        #pragma unroll 8
        for (int k = 0; k < HIDDEN; k++)
            acc = fmaf(sp[k], __ldg(W1 + k * 64 + t), acc);
        val = fmaxf(acc, 0.f) * __ldg(W2 + t);
    }
    sred[t] = val;
    __syncthreads();
    for (int s = 64; s > 0; s >>= 1) {
        if (t < s) sred[t] += sred[t + s];
        __syncthreads();
    }
    if (t == 0) out[g] = sred[0] + __ldg(b2);
}

// -------------------------------------------------------------------------
extern "C" void kernel_launch(void* const* d_in, const int* in_sizes, int n_in,
                              void* d_out, int out_size)
{
    (void)in_sizes; (void)n_in; (void)out_size;
    const float* x     = (const float*)d_in[0];
    const int*   ei    = (const int*)  d_in[1];
    const float* ea    = (const float*)d_in[2];
    const int*   batch = (const int*)  d_in[3];
    const float* P[21];
    for (int i = 0; i < 21; i++) P[i] = (const float*)d_in[4 + i];
    const float* head_w1 = (const float*)d_in[25];
    const float* head_b1 = (const float*)d_in[26];
    const float* head_w2 = (const float*)d_in[27];
    const float* head_b2 = (const float*)d_in[28];
    float* out = (float*)d_out;

    float *hr, *ho, *ha, *hb, *scale, *shift;
    uint32_t* Bf;
    int *dc, *incl, *bsum, *boff, *csr_src;
    float *csr_ew;
    cudaGetSymbolAddress((void**)&hr,      g_hr);
    cudaGetSymbolAddress((void**)&ho,      g_ho);
    cudaGetSymbolAddress((void**)&ha,      g_ha);
    cudaGetSymbolAddress((void**)&hb,      g_hb);
    cudaGetSymbolAddress((void**)&scale,   g_scale);
    cudaGetSymbolAddress((void**)&shift,   g_shift);
    cudaGetSymbolAddress((void**)&Bf,      g_Bf);
    cudaGetSymbolAddress((void**)&dc,      g_dc);
    cudaGetSymbolAddress((void**)&incl,    g_incl);
    cudaGetSymbolAddress((void**)&bsum,    g_bsum);
    cudaGetSymbolAddress((void**)&boff,    g_boff);
    cudaGetSymbolAddress((void**)&csr_src, g_csr_src);
    cudaGetSymbolAddress((void**)&csr_ew,  g_csr_ew);

    int* deg    = dc;
    int* cursor = dc + N_NODES;

    cudaFuncSetAttribute(gemm_fused_kernel<64>,
                         cudaFuncAttributeMaxDynamicSharedMemorySize, GEMM_FUSED_SMEM);
    cudaFuncSetAttribute(gemm_mma_kernel<8>,
                         cudaFuncAttributeMaxDynamicSharedMemorySize, GEMM_SMEM(128));

    const int* src = ei;
    const int* dst = ei + N_EDGES;

    const int gather_blocks = (N_NODES * 32 + 255) / 256;

    // Launch order: #6 (ncu -s 5 -c 1, memset counted) = gather64 (layer-0 gather).
    cudaMemsetAsync(dc, 0, 2 * N_NODES * sizeof(int), 0);               // 1
    hist_kernel<<<(N_EDGES + 255) / 256, 256>>>(dst, deg);              // 2
    scan1_kernel<<<N_SCAN_BLOCKS, SCAN_BLK>>>(deg, incl, bsum);         // 3
    scan2_kernel<<<1, 512>>>(bsum, boff);                               // 4
    fill_kernel<<<(N_EDGES + 255) / 256, 256>>>(src, dst, ea, deg, incl, boff,
                                                cursor, csr_src, csr_ew); // 5
    gather64_kernel<<<gather_blocks, 256>>>(x, deg, incl, boff,
                                            csr_src, csr_ew, ho);       // 6 (profiled; ho = agg0)
    prep0_kernel<<<16384 / 256, 256>>>(P[0], P[2]);                     // 7
    prep12_kernel<<<65536 / 256, 256>>>(P[7], P[9], P[14], P[16]);      // 8
    bn_fold_kernel<<<3, 128>>>(P[1], P[3], P[4], P[5], P[6],
                               P[8], P[10], P[11], P[12], P[13],
                               P[15], P[17], P[18], P[19], P[20]);      // 9

    // ---- Layer 0 (gather-first, fused): [agg0 | x] @ [Wr0;Wo0] + BN + ReLU -> ha
    gemm_fused_kernel<64><<<N_TILES64, 128, GEMM_FUSED_SMEM>>>(
        ho, x, Bf, scale + 0 * HIDDEN, shift + 0 * HIDDEN, ha);         // 10

    // ---- Layer 1 (GEMM-first) ----
    gemm_mma_kernel<8><<<N_TILES64, 256, GEMM_SMEM(128)>>>(ha, Bf + 16384, hr, ho);
    gather_fused_kernel<<<gather_blocks, 256>>>(hr, ho, deg, incl, boff,
                                                csr_src, csr_ew,
                                                scale + 1 * HIDDEN, shift + 1 * HIDDEN, hb);

    // ---- Layer 2 (GEMM-first) ----
    gemm_mma_kernel<8><<<N_TILES64, 256, GEMM_SMEM(128)>>>(hb, Bf + 49152, hr, ho);
    gather_fused_kernel<<<gather_blocks, 256>>>(hr, ho, deg, incl, boff,
                                                csr_src, csr_ew,
                                                scale + 2 * HIDDEN, shift + 2 * HIDDEN, ha);

    // ---- Fused mean pool + head ----
    pool_head_kernel<<<N_GRAPHS, 128>>>(ha, batch, head_w1, head_b1,
                                        head_w2, head_b2, out);
}